// round 5
// baseline (speedup 1.0000x reference)
#include <cuda_runtime.h>
#include <cuda_bf16.h>

#define ZD 21
#define YD 256
#define XD 256
#define CIN 16
#define C1 32
#define C2 64
#define BN_EPS 1e-3f
#define GRID_SZ (2 * ZD * YD * XD)   // 2,752,512
#define NMAX 400000
#define FULLW 0xffffffffu
#define ROWVALID 64   // mask bit: this row exists

__device__ int   g_grid[GRID_SZ];
__device__ float g_f1[NMAX * C1];

// packed dual-FMA: d.lo += a.lo*b.lo ; d.hi += a.hi*b.hi  (exact IEEE per lane)
__device__ __forceinline__ void ffma2(unsigned long long& d,
                                      unsigned long long a,
                                      unsigned long long b) {
    asm("fma.rn.f32x2 %0, %1, %2, %0;" : "+l"(d) : "l"(a), "l"(b));
}
__device__ __forceinline__ float f2sum(unsigned long long v) {
    float lo, hi;
    asm("mov.b64 {%0,%1}, %2;" : "=f"(lo), "=f"(hi) : "l"(v));
    return lo + hi;
}

// ---------------------------------------------------------------------------
// Hash-grid build
// ---------------------------------------------------------------------------
__global__ void fill_grid_kernel() {
    int i = blockIdx.x * blockDim.x + threadIdx.x;
    if (i < GRID_SZ / 4) {
        ((int4*)g_grid)[i] = make_int4(-1, -1, -1, -1);
    }
}

__global__ void scatter_kernel(const int* __restrict__ coors, int n) {
    int i = blockIdx.x * blockDim.x + threadIdx.x;
    if (i < n) {
        int4 c = ((const int4*)coors)[i];  // (b, z, y, x)
        int lin = ((c.x * ZD + c.y) * YD + c.z) * XD + c.w;
        g_grid[lin] = i;
    }
}

// ---------------------------------------------------------------------------
// Probes (per-lane; lanes holding no row have msk=0 -> always -1)
// ---------------------------------------------------------------------------
__device__ __forceinline__ int probe1(int k, int lin, int msk) {
    int dz = k / 9 - 1, dy = (k / 3) % 3 - 1, dx = k % 3 - 1;
    int req = ((dz < 0) ? 1 : 0) | ((dz > 0) ? 2 : 0) |
              ((dy < 0) ? 4 : 0) | ((dy > 0) ? 8 : 0) |
              ((dx < 0) ? 16 : 0) | ((dx > 0) ? 32 : 0) | ROWVALID;
    int koff = (dz * YD + dy) * XD + dx;
    return ((msk & req) == req) ? __ldg(&g_grid[lin + koff]) : -1;
}

__device__ __forceinline__ int probe2(int k, int lin, int msk) {
    int jz = k / 9, jy = (k / 3) % 3, jx = k % 3;
    int req = ((jy == 0) ? 1 : 0) | ((jx == 0) ? 2 : 0) | ROWVALID;
    int koff = (jz * YD + jy) * XD + jx;
    return ((msk & req) == req) ? __ldg(&g_grid[lin + koff]) : -1;
}

extern __shared__ float smw[];

// ---------------------------------------------------------------------------
// Layer 1: SubMConv3d k=3 pad=1, CIN=16 -> C1=32, fused BN+ReLU
// 512 thr = 16 warps, 2 blocks/SM. Warp owns 16 rows, lane = cout.
// k-outer, per-k register weights (8 x f32x2), depth-2 probe prefetch,
// packed FFMA2 accumulation.
// ---------------------------------------------------------------------------
__global__ __launch_bounds__(512, 2) void conv1_kernel(
    const float* __restrict__ feat, const int* __restrict__ coors,
    const float* __restrict__ W1,
    const float* __restrict__ g1, const float* __restrict__ b1,
    const float* __restrict__ m1, const float* __restrict__ v1,
    int n)
{
    // Stage W1[k][ci][co] -> smw[(k*32+co)*32 + (chunk^(co&7))*4 + pos], chunk=ci/4
    for (int e = threadIdx.x; e < 27 * CIN * C1; e += blockDim.x) {
        int k   = e / (CIN * C1);
        int rem = e % (CIN * C1);
        int ci  = rem / C1;
        int co  = rem % C1;
        int chunk = ci >> 2, pos = ci & 3;
        int sch = chunk ^ (co & 7);
        smw[(k * 32 + co) * 32 + sch * 4 + pos] = W1[e];
    }
    __syncthreads();

    int warp = threadIdx.x >> 5;
    int lane = threadIdx.x & 31;
    int row0 = blockIdx.x * 256 + warp * 16;

    int lin = 0, msk = 0;
    if (lane < 16) {
        int r = row0 + lane;
        if (r < n) {
            int4 c = ((const int4*)coors)[r];  // (b, z, y, x)
            lin = ((c.x * ZD + c.y) * YD + c.z) * XD + c.w;
            msk = (c.y > 0)             |
                  ((c.y < ZD - 1) << 1) |
                  ((c.z > 0)      << 2) |
                  ((c.z < YD - 1) << 3) |
                  ((c.w > 0)      << 4) |
                  ((c.w < XD - 1) << 5) |
                  ROWVALID;
        }
    }

    unsigned long long acc[16];
    #pragma unroll
    for (int r = 0; r < 16; r++) acc[r] = 0ull;

    const ulonglong2* featv = (const ulonglong2*)feat;   // row = 4 x ulonglong2
    int swz = (lane & 7) * 4;

    int cur = probe1(0, lin, msk);
    int nx1 = probe1(1, lin, msk);
    #pragma unroll 1
    for (int k = 0; k < 27; k++) {
        int nx2 = (k < 25) ? probe1(k + 2, lin, msk) : -1;
        unsigned mask = __ballot_sync(FULLW, cur >= 0) & 0xffffu;
        if (mask) {
            const float* wrow = &smw[(k * 32 + lane) * 32];
            ulonglong2 w0 = *(const ulonglong2*)&wrow[(0 * 4) ^ swz];
            ulonglong2 w1 = *(const ulonglong2*)&wrow[(1 * 4) ^ swz];
            ulonglong2 w2 = *(const ulonglong2*)&wrow[(2 * 4) ^ swz];
            ulonglong2 w3 = *(const ulonglong2*)&wrow[(3 * 4) ^ swz];
            #pragma unroll
            for (int r = 0; r < 16; r++) {
                if ((mask >> r) & 1) {   // warp-uniform
                    int idx = __shfl_sync(FULLW, cur, r);
                    const ulonglong2* fp = &featv[idx * 4];
                    ulonglong2 f0 = __ldg(fp + 0);
                    ulonglong2 f1 = __ldg(fp + 1);
                    ulonglong2 f2 = __ldg(fp + 2);
                    ulonglong2 f3 = __ldg(fp + 3);
                    ffma2(acc[r], f0.x, w0.x); ffma2(acc[r], f0.y, w0.y);
                    ffma2(acc[r], f1.x, w1.x); ffma2(acc[r], f1.y, w1.y);
                    ffma2(acc[r], f2.x, w2.x); ffma2(acc[r], f2.y, w2.y);
                    ffma2(acc[r], f3.x, w3.x); ffma2(acc[r], f3.y, w3.y);
                }
            }
        }
        cur = nx1; nx1 = nx2;
    }

    float s  = g1[lane] * rsqrtf(v1[lane] + BN_EPS);
    float sh = b1[lane] - m1[lane] * s;
    #pragma unroll
    for (int r = 0; r < 16; r++) {
        int row = row0 + r;
        if (row < n) {
            float o = fmaf(f2sum(acc[r]), s, sh);
            g_f1[row * C1 + lane] = o > 0.f ? o : 0.f;
        }
    }
}

// ---------------------------------------------------------------------------
// Layer 2: SparseConv3d k=3 s=2 pad=(0,1,1), C1=32 -> C2=64, fused BN+ReLU
// Cout halves split ACROSS BLOCKS (smem 110.6KB -> 2 blocks/SM).
// 512 thr = 16 warps; warp owns 16 rows, lane = local cout.
// Per k: two ci-half passes, each with 16 regs of f32x2 weights; FFMA2.
// NOTE: base lin may be legitimately negative; validity lives in ROWVALID bit.
// ---------------------------------------------------------------------------
__global__ __launch_bounds__(512, 2) void conv2_kernel(
    const int* __restrict__ ocoors, const float* __restrict__ W2,
    const float* __restrict__ g2, const float* __restrict__ b2,
    const float* __restrict__ m2, const float* __restrict__ v2,
    float* __restrict__ out, int m)
{
    int half = blockIdx.x & 1;

    // Stage W2[k][ci][half*32+col] -> smw[(k*32+col)*32 + (chunk^(col&7))*4 + pos]
    for (int e = threadIdx.x; e < 27 * C1 * 32; e += blockDim.x) {
        int k   = e / (C1 * 32);
        int rem = e % (C1 * 32);
        int ci  = rem / 32;
        int col = rem % 32;
        int chunk = ci >> 2, pos = ci & 3;
        int sch = chunk ^ (col & 7);
        smw[(k * 32 + col) * 32 + sch * 4 + pos] =
            W2[(k * C1 + ci) * C2 + half * 32 + col];
    }
    __syncthreads();

    int warp = threadIdx.x >> 5;
    int lane = threadIdx.x & 31;
    int row0 = (blockIdx.x >> 1) * 256 + warp * 16;

    int lin = 0, msk = 0;
    if (lane < 16) {
        int r = row0 + lane;
        if (r < m) {
            int4 c = ((const int4*)ocoors)[r];  // (b, oz, oy, ox)
            int z0 = c.y * 2;
            int y0 = c.z * 2 - 1;
            int x0 = c.w * 2 - 1;
            lin = ((c.x * ZD + z0) * YD + y0) * XD + x0;   // may be < 0, OK
            msk = (c.z > 0) | ((c.w > 0) << 1) | ROWVALID;
        }
    }

    unsigned long long acc[16];
    #pragma unroll
    for (int r = 0; r < 16; r++) acc[r] = 0ull;

    const ulonglong2* f1v = (const ulonglong2*)g_f1;    // row = 8 x ulonglong2
    int swz = (lane & 7) * 4;

    int cur = probe2(0, lin, msk);
    int nx1 = probe2(1, lin, msk);
    #pragma unroll 1
    for (int k = 0; k < 27; k++) {
        int nx2 = (k < 25) ? probe2(k + 2, lin, msk) : -1;
        unsigned mask = __ballot_sync(FULLW, cur >= 0) & 0xffffu;
        if (mask) {
            const float* wrow = &smw[(k * 32 + lane) * 32];
            #pragma unroll
            for (int cc = 0; cc < 2; cc++) {
                ulonglong2 w0 = *(const ulonglong2*)&wrow[((cc * 4 + 0) * 4) ^ swz];
                ulonglong2 w1 = *(const ulonglong2*)&wrow[((cc * 4 + 1) * 4) ^ swz];
                ulonglong2 w2 = *(const ulonglong2*)&wrow[((cc * 4 + 2) * 4) ^ swz];
                ulonglong2 w3 = *(const ulonglong2*)&wrow[((cc * 4 + 3) * 4) ^ swz];
                #pragma unroll
                for (int r = 0; r < 16; r++) {
                    if ((mask >> r) & 1) {   // warp-uniform
                        int idx = __shfl_sync(FULLW, cur, r);
                        const ulonglong2* fp = &f1v[idx * 8 + cc * 4];
                        ulonglong2 f0 = __ldg(fp + 0);
                        ulonglong2 f1 = __ldg(fp + 1);
                        ulonglong2 f2 = __ldg(fp + 2);
                        ulonglong2 f3 = __ldg(fp + 3);
                        ffma2(acc[r], f0.x, w0.x); ffma2(acc[r], f0.y, w0.y);
                        ffma2(acc[r], f1.x, w1.x); ffma2(acc[r], f1.y, w1.y);
                        ffma2(acc[r], f2.x, w2.x); ffma2(acc[r], f2.y, w2.y);
                        ffma2(acc[r], f3.x, w3.x); ffma2(acc[r], f3.y, w3.y);
                    }
                }
            }
        }
        cur = nx1; nx1 = nx2;
    }

    int co = half * 32 + lane;
    float s  = g2[co] * rsqrtf(v2[co] + BN_EPS);
    float sh = b2[co] - m2[co] * s;
    #pragma unroll
    for (int r = 0; r < 16; r++) {
        int row = row0 + r;
        if (row < m) {
            float o = fmaf(f2sum(acc[r]), s, sh);
            out[row * C2 + co] = o > 0.f ? o : 0.f;
        }
    }
}

// ---------------------------------------------------------------------------
// Tail: fill everything past f2 (out_coors as float, batch_size) if the
// harness flattened the full reference tuple into d_out.
// ---------------------------------------------------------------------------
__global__ void tail_kernel(const int* __restrict__ ocoors,
                            const int* __restrict__ bsz,
                            float* __restrict__ out, int m, int total)
{
    int i = blockIdx.x * blockDim.x + threadIdx.x + m * 64;
    if (i >= total) return;
    int j = i - m * 64;
    float v;
    if (j < m * 4)       v = (float)ocoors[j];
    else if (j == m * 4) v = (float)bsz[0];
    else                 v = 0.f;
    out[i] = v;
}

// ---------------------------------------------------------------------------
extern "C" void kernel_launch(void* const* d_in, const int* in_sizes, int n_in,
                              void* d_out, int out_size)
{
    const float* feat   = (const float*)d_in[0];
    const int*   coors  = (const int*)d_in[1];
    const int*   ocoors = (const int*)d_in[2];
    const float* W1     = (const float*)d_in[3];
    const float* g1     = (const float*)d_in[4];
    const float* b1     = (const float*)d_in[5];
    const float* m1     = (const float*)d_in[6];
    const float* v1     = (const float*)d_in[7];
    const float* W2     = (const float*)d_in[8];
    const float* g2     = (const float*)d_in[9];
    const float* b2     = (const float*)d_in[10];
    const float* m2     = (const float*)d_in[11];
    const float* v2     = (const float*)d_in[12];
    const int*   bsz    = (const int*)d_in[13];

    int n = in_sizes[0] / CIN;
    int m = in_sizes[2] / 4;

    fill_grid_kernel<<<(GRID_SZ / 4 + 255) / 256, 256>>>();
    scatter_kernel<<<(n + 255) / 256, 256>>>(coors, n);

    int smem1 = 27 * C1 * 32 * (int)sizeof(float);   // 110,592 B
    cudaFuncSetAttribute(conv1_kernel, cudaFuncAttributeMaxDynamicSharedMemorySize, smem1);
    conv1_kernel<<<(n + 255) / 256, 512, smem1>>>(feat, coors, W1, g1, b1, m1, v1, n);

    int smem2 = 27 * 32 * 32 * (int)sizeof(float);   // 110,592 B (half of W2)
    cudaFuncSetAttribute(conv2_kernel, cudaFuncAttributeMaxDynamicSharedMemorySize, smem2);
    int rowblocks = (m + 255) / 256;
    conv2_kernel<<<rowblocks * 2, 512, smem2>>>(ocoors, W2, g2, b2, m2, v2,
                                                (float*)d_out, m);

    int tail = out_size - m * 64;
    if (tail > 0) {
        tail_kernel<<<(tail + 255) / 256, 256>>>(ocoors, bsz, (float*)d_out, m, out_size);
    }
}

// round 6
// speedup vs baseline: 1.0880x; 1.0880x over previous
#include <cuda_runtime.h>
#include <cuda_bf16.h>

#define ZD 21
#define YD 256
#define XD 256
#define CIN 16
#define C1 32
#define C2 64
#define BN_EPS 1e-3f
#define GRID_SZ (2 * ZD * YD * XD)   // 2,752,512
#define NMAX 400000
#define FULLW 0xffffffffu
#define ROWVALID 64   // mask bit: this row exists

__device__ int   g_grid[GRID_SZ];
__device__ float g_f1[NMAX * C1];

// ---------------------------------------------------------------------------
// Hash-grid build
// ---------------------------------------------------------------------------
__global__ void fill_grid_kernel() {
    int i = blockIdx.x * blockDim.x + threadIdx.x;
    if (i < GRID_SZ / 4) {
        ((int4*)g_grid)[i] = make_int4(-1, -1, -1, -1);
    }
}

__global__ void scatter_kernel(const int* __restrict__ coors, int n) {
    int i = blockIdx.x * blockDim.x + threadIdx.x;
    if (i < n) {
        int4 c = ((const int4*)coors)[i];  // (b, z, y, x)
        int lin = ((c.x * ZD + c.y) * YD + c.z) * XD + c.w;
        g_grid[lin] = i;
    }
}

// ---------------------------------------------------------------------------
// Probes (per-lane; lanes holding no row have msk=0 -> always -1)
// ---------------------------------------------------------------------------
__device__ __forceinline__ int probe1(int k, int lin, int msk) {
    int dz = k / 9 - 1, dy = (k / 3) % 3 - 1, dx = k % 3 - 1;
    int req = ((dz < 0) ? 1 : 0) | ((dz > 0) ? 2 : 0) |
              ((dy < 0) ? 4 : 0) | ((dy > 0) ? 8 : 0) |
              ((dx < 0) ? 16 : 0) | ((dx > 0) ? 32 : 0) | ROWVALID;
    int koff = (dz * YD + dy) * XD + dx;
    return ((msk & req) == req) ? __ldg(&g_grid[lin + koff]) : -1;
}

__device__ __forceinline__ int probe2(int k, int lin, int msk) {
    int jz = k / 9, jy = (k / 3) % 3, jx = k % 3;
    int req = ((jy == 0) ? 1 : 0) | ((jx == 0) ? 2 : 0) | ROWVALID;
    int koff = (jz * YD + jy) * XD + jx;
    return ((msk & req) == req) ? __ldg(&g_grid[lin + koff]) : -1;
}

extern __shared__ float smw[];

// ---------------------------------------------------------------------------
// Layer 1: SubMConv3d k=3 pad=1, CIN=16 -> C1=32, fused BN+ReLU
// 256 thr = 8 warps, 2 blocks/SM (512 thr/SM -> 128 regs/thread).
// Warp owns 16 rows, lane = cout. k-outer, per-k register weights,
// depth-2 probe prefetch, SPLIT accumulator chains + 4 distinct f regs.
// ---------------------------------------------------------------------------
__global__ __launch_bounds__(256, 2) void conv1_kernel(
    const float* __restrict__ feat, const int* __restrict__ coors,
    const float* __restrict__ W1,
    const float* __restrict__ g1, const float* __restrict__ b1,
    const float* __restrict__ m1, const float* __restrict__ v1,
    int n)
{
    // Stage W1[k][ci][co] -> smw[(k*32+co)*32 + (chunk^(co&7))*4 + pos], chunk=ci/4
    for (int e = threadIdx.x; e < 27 * CIN * C1; e += blockDim.x) {
        int k   = e / (CIN * C1);
        int rem = e % (CIN * C1);
        int ci  = rem / C1;
        int co  = rem % C1;
        int chunk = ci >> 2, pos = ci & 3;
        int sch = chunk ^ (co & 7);
        smw[(k * 32 + co) * 32 + sch * 4 + pos] = W1[e];
    }
    __syncthreads();

    int warp = threadIdx.x >> 5;
    int lane = threadIdx.x & 31;
    int row0 = blockIdx.x * 128 + warp * 16;

    int lin = 0, msk = 0;
    if (lane < 16) {
        int r = row0 + lane;
        if (r < n) {
            int4 c = ((const int4*)coors)[r];  // (b, z, y, x)
            lin = ((c.x * ZD + c.y) * YD + c.z) * XD + c.w;
            msk = (c.y > 0)             |
                  ((c.y < ZD - 1) << 1) |
                  ((c.z > 0)      << 2) |
                  ((c.z < YD - 1) << 3) |
                  ((c.w > 0)      << 4) |
                  ((c.w < XD - 1) << 5) |
                  ROWVALID;
        }
    }

    float accA[16], accB[16];   // split chains: ci 0-7 / ci 8-15
    #pragma unroll
    for (int r = 0; r < 16; r++) { accA[r] = 0.f; accB[r] = 0.f; }

    const float4* feat4 = (const float4*)feat;
    int swz = (lane & 7) * 4;

    int cur = probe1(0, lin, msk);
    int nx1 = probe1(1, lin, msk);
    #pragma unroll 1
    for (int k = 0; k < 27; k++) {
        int nx2 = (k < 25) ? probe1(k + 2, lin, msk) : -1;
        unsigned mask = __ballot_sync(FULLW, cur >= 0) & 0xffffu;
        if (mask) {
            const float* wrow = &smw[(k * 32 + lane) * 32];
            float4 w0 = *(const float4*)&wrow[(0 * 4) ^ swz];
            float4 w1 = *(const float4*)&wrow[(1 * 4) ^ swz];
            float4 w2 = *(const float4*)&wrow[(2 * 4) ^ swz];
            float4 w3 = *(const float4*)&wrow[(3 * 4) ^ swz];
            #pragma unroll
            for (int r = 0; r < 16; r++) {
                if ((mask >> r) & 1) {   // warp-uniform
                    int idx = __shfl_sync(FULLW, cur, r);
                    const float4* fp = &feat4[idx * 4];
                    float4 f0 = __ldg(fp + 0);
                    float4 f1 = __ldg(fp + 1);
                    float4 f2 = __ldg(fp + 2);
                    float4 f3 = __ldg(fp + 3);
                    float a = accA[r], b = accB[r];
                    a = fmaf(f0.x, w0.x, a); a = fmaf(f0.y, w0.y, a);
                    a = fmaf(f0.z, w0.z, a); a = fmaf(f0.w, w0.w, a);
                    b = fmaf(f2.x, w2.x, b); b = fmaf(f2.y, w2.y, b);
                    b = fmaf(f2.z, w2.z, b); b = fmaf(f2.w, w2.w, b);
                    a = fmaf(f1.x, w1.x, a); a = fmaf(f1.y, w1.y, a);
                    a = fmaf(f1.z, w1.z, a); a = fmaf(f1.w, w1.w, a);
                    b = fmaf(f3.x, w3.x, b); b = fmaf(f3.y, w3.y, b);
                    b = fmaf(f3.z, w3.z, b); b = fmaf(f3.w, w3.w, b);
                    accA[r] = a; accB[r] = b;
                }
            }
        }
        cur = nx1; nx1 = nx2;
    }

    float s  = g1[lane] * rsqrtf(v1[lane] + BN_EPS);
    float sh = b1[lane] - m1[lane] * s;
    #pragma unroll
    for (int r = 0; r < 16; r++) {
        int row = row0 + r;
        if (row < n) {
            float o = fmaf(accA[r] + accB[r], s, sh);
            g_f1[row * C1 + lane] = o > 0.f ? o : 0.f;
        }
    }
}

// ---------------------------------------------------------------------------
// Layer 2: SparseConv3d k=3 s=2 pad=(0,1,1), C1=32 -> C2=64, fused BN+ReLU
// Cout halves split ACROSS BLOCKS (smem 110.6KB -> 2 blocks/SM).
// 256 thr = 8 warps (512 thr/SM -> 128 regs); warp owns 16 rows, lane = cout.
// Per k: 8 register float4 weights; per pair: 8 DISTINCT f regs (full MLP),
// accumulator split into two 16-FMA chains.
// NOTE: base lin may be legitimately negative; validity lives in ROWVALID bit.
// ---------------------------------------------------------------------------
__global__ __launch_bounds__(256, 2) void conv2_kernel(
    const int* __restrict__ ocoors, const float* __restrict__ W2,
    const float* __restrict__ g2, const float* __restrict__ b2,
    const float* __restrict__ m2, const float* __restrict__ v2,
    float* __restrict__ out, int m)
{
    int half = blockIdx.x & 1;

    // Stage W2[k][ci][half*32+col] -> smw[(k*32+col)*32 + (chunk^(col&7))*4 + pos]
    for (int e = threadIdx.x; e < 27 * C1 * 32; e += blockDim.x) {
        int k   = e / (C1 * 32);
        int rem = e % (C1 * 32);
        int ci  = rem / 32;
        int col = rem % 32;
        int chunk = ci >> 2, pos = ci & 3;
        int sch = chunk ^ (col & 7);
        smw[(k * 32 + col) * 32 + sch * 4 + pos] =
            W2[(k * C1 + ci) * C2 + half * 32 + col];
    }
    __syncthreads();

    int warp = threadIdx.x >> 5;
    int lane = threadIdx.x & 31;
    int row0 = (blockIdx.x >> 1) * 128 + warp * 16;

    int lin = 0, msk = 0;
    if (lane < 16) {
        int r = row0 + lane;
        if (r < m) {
            int4 c = ((const int4*)ocoors)[r];  // (b, oz, oy, ox)
            int z0 = c.y * 2;
            int y0 = c.z * 2 - 1;
            int x0 = c.w * 2 - 1;
            lin = ((c.x * ZD + z0) * YD + y0) * XD + x0;   // may be < 0, OK
            msk = (c.z > 0) | ((c.w > 0) << 1) | ROWVALID;
        }
    }

    float accA[16], accB[16];   // split chains: ci 0-15 / ci 16-31
    #pragma unroll
    for (int r = 0; r < 16; r++) { accA[r] = 0.f; accB[r] = 0.f; }

    const float4* f14 = (const float4*)g_f1;
    int swz = (lane & 7) * 4;

    int cur = probe2(0, lin, msk);
    int nx1 = probe2(1, lin, msk);
    #pragma unroll 1
    for (int k = 0; k < 27; k++) {
        int nx2 = (k < 25) ? probe2(k + 2, lin, msk) : -1;
        unsigned mask = __ballot_sync(FULLW, cur >= 0) & 0xffffu;
        if (mask) {
            const float* wrow = &smw[(k * 32 + lane) * 32];
            float4 w0 = *(const float4*)&wrow[(0 * 4) ^ swz];
            float4 w1 = *(const float4*)&wrow[(1 * 4) ^ swz];
            float4 w2 = *(const float4*)&wrow[(2 * 4) ^ swz];
            float4 w3 = *(const float4*)&wrow[(3 * 4) ^ swz];
            float4 w4 = *(const float4*)&wrow[(4 * 4) ^ swz];
            float4 w5 = *(const float4*)&wrow[(5 * 4) ^ swz];
            float4 w6 = *(const float4*)&wrow[(6 * 4) ^ swz];
            float4 w7 = *(const float4*)&wrow[(7 * 4) ^ swz];
            #pragma unroll
            for (int r = 0; r < 16; r++) {
                if ((mask >> r) & 1) {   // warp-uniform
                    int idx = __shfl_sync(FULLW, cur, r);
                    const float4* fp = &f14[idx * 8];
                    float4 f0 = __ldg(fp + 0);
                    float4 f1 = __ldg(fp + 1);
                    float4 f2 = __ldg(fp + 2);
                    float4 f3 = __ldg(fp + 3);
                    float4 f4 = __ldg(fp + 4);
                    float4 f5 = __ldg(fp + 5);
                    float4 f6 = __ldg(fp + 6);
                    float4 f7 = __ldg(fp + 7);
                    float a = accA[r], b = accB[r];
                    a = fmaf(f0.x, w0.x, a); a = fmaf(f0.y, w0.y, a);
                    a = fmaf(f0.z, w0.z, a); a = fmaf(f0.w, w0.w, a);
                    b = fmaf(f4.x, w4.x, b); b = fmaf(f4.y, w4.y, b);
                    b = fmaf(f4.z, w4.z, b); b = fmaf(f4.w, w4.w, b);
                    a = fmaf(f1.x, w1.x, a); a = fmaf(f1.y, w1.y, a);
                    a = fmaf(f1.z, w1.z, a); a = fmaf(f1.w, w1.w, a);
                    b = fmaf(f5.x, w5.x, b); b = fmaf(f5.y, w5.y, b);
                    b = fmaf(f5.z, w5.z, b); b = fmaf(f5.w, w5.w, b);
                    a = fmaf(f2.x, w2.x, a); a = fmaf(f2.y, w2.y, a);
                    a = fmaf(f2.z, w2.z, a); a = fmaf(f2.w, w2.w, a);
                    b = fmaf(f6.x, w6.x, b); b = fmaf(f6.y, w6.y, b);
                    b = fmaf(f6.z, w6.z, b); b = fmaf(f6.w, w6.w, b);
                    a = fmaf(f3.x, w3.x, a); a = fmaf(f3.y, w3.y, a);
                    a = fmaf(f3.z, w3.z, a); a = fmaf(f3.w, w3.w, a);
                    b = fmaf(f7.x, w7.x, b); b = fmaf(f7.y, w7.y, b);
                    b = fmaf(f7.z, w7.z, b); b = fmaf(f7.w, w7.w, b);
                    accA[r] = a; accB[r] = b;
                }
            }
        }
        cur = nx1; nx1 = nx2;
    }

    int co = half * 32 + lane;
    float s  = g2[co] * rsqrtf(v2[co] + BN_EPS);
    float sh = b2[co] - m2[co] * s;
    #pragma unroll
    for (int r = 0; r < 16; r++) {
        int row = row0 + r;
        if (row < m) {
            float o = fmaf(accA[r] + accB[r], s, sh);
            out[row * C2 + co] = o > 0.f ? o : 0.f;
        }
    }
}

// ---------------------------------------------------------------------------
// Tail: fill everything past f2 (out_coors as float, batch_size) if the
// harness flattened the full reference tuple into d_out.
// ---------------------------------------------------------------------------
__global__ void tail_kernel(const int* __restrict__ ocoors,
                            const int* __restrict__ bsz,
                            float* __restrict__ out, int m, int total)
{
    int i = blockIdx.x * blockDim.x + threadIdx.x + m * 64;
    if (i >= total) return;
    int j = i - m * 64;
    float v;
    if (j < m * 4)       v = (float)ocoors[j];
    else if (j == m * 4) v = (float)bsz[0];
    else                 v = 0.f;
    out[i] = v;
}

// ---------------------------------------------------------------------------
extern "C" void kernel_launch(void* const* d_in, const int* in_sizes, int n_in,
                              void* d_out, int out_size)
{
    const float* feat   = (const float*)d_in[0];
    const int*   coors  = (const int*)d_in[1];
    const int*   ocoors = (const int*)d_in[2];
    const float* W1     = (const float*)d_in[3];
    const float* g1     = (const float*)d_in[4];
    const float* b1     = (const float*)d_in[5];
    const float* m1     = (const float*)d_in[6];
    const float* v1     = (const float*)d_in[7];
    const float* W2     = (const float*)d_in[8];
    const float* g2     = (const float*)d_in[9];
    const float* b2     = (const float*)d_in[10];
    const float* m2     = (const float*)d_in[11];
    const float* v2     = (const float*)d_in[12];
    const int*   bsz    = (const int*)d_in[13];

    int n = in_sizes[0] / CIN;
    int m = in_sizes[2] / 4;

    fill_grid_kernel<<<(GRID_SZ / 4 + 255) / 256, 256>>>();
    scatter_kernel<<<(n + 255) / 256, 256>>>(coors, n);

    int smem1 = 27 * C1 * 32 * (int)sizeof(float);   // 110,592 B
    cudaFuncSetAttribute(conv1_kernel, cudaFuncAttributeMaxDynamicSharedMemorySize, smem1);
    conv1_kernel<<<(n + 127) / 128, 256, smem1>>>(feat, coors, W1, g1, b1, m1, v1, n);

    int smem2 = 27 * 32 * 32 * (int)sizeof(float);   // 110,592 B (half of W2)
    cudaFuncSetAttribute(conv2_kernel, cudaFuncAttributeMaxDynamicSharedMemorySize, smem2);
    int rowblocks = (m + 127) / 128;
    conv2_kernel<<<rowblocks * 2, 256, smem2>>>(ocoors, W2, g2, b2, m2, v2,
                                                (float*)d_out, m);

    int tail = out_size - m * 64;
    if (tail > 0) {
        tail_kernel<<<(tail + 255) / 256, 256>>>(ocoors, bsz, (float*)d_out, m, out_size);
    }
}

// round 7
// speedup vs baseline: 1.1432x; 1.0508x over previous
#include <cuda_runtime.h>
#include <cuda_bf16.h>

#define ZD 21
#define YD 256
#define XD 256
#define CIN 16
#define C1 32
#define C2 64
#define BN_EPS 1e-3f
#define GRID_SZ (2 * ZD * YD * XD)   // 2,752,512
#define NMAX 400000
#define FULLW 0xffffffffu
#define ROWVALID 64   // mask bit: this row exists
#define SENT 0xffffffffu   // merge sentinel: k-field = 8191, never matches

__device__ int      g_grid[GRID_SZ];
__device__ float    g_f1[NMAX * C1];
__device__ unsigned g_rb[27 * NMAX];   // slot-major: rb[e*NMAX + row], reused by both layers
__device__ int      g_cnt[NMAX];

// ---------------------------------------------------------------------------
// Hash-grid build
// ---------------------------------------------------------------------------
__global__ void fill_grid_kernel() {
    int i = blockIdx.x * blockDim.x + threadIdx.x;
    if (i < GRID_SZ / 4) {
        ((int4*)g_grid)[i] = make_int4(-1, -1, -1, -1);
    }
}

__global__ void scatter_kernel(const int* __restrict__ coors, int n) {
    int i = blockIdx.x * blockDim.x + threadIdx.x;
    if (i < n) {
        int4 c = ((const int4*)coors)[i];  // (b, z, y, x)
        int lin = ((c.x * ZD + c.y) * YD + c.z) * XD + c.w;
        g_grid[lin] = i;
    }
}

// ---------------------------------------------------------------------------
// Probes
// ---------------------------------------------------------------------------
__device__ __forceinline__ int probe1(int k, int lin, int msk) {
    int dz = k / 9 - 1, dy = (k / 3) % 3 - 1, dx = k % 3 - 1;
    int req = ((dz < 0) ? 1 : 0) | ((dz > 0) ? 2 : 0) |
              ((dy < 0) ? 4 : 0) | ((dy > 0) ? 8 : 0) |
              ((dx < 0) ? 16 : 0) | ((dx > 0) ? 32 : 0) | ROWVALID;
    int koff = (dz * YD + dy) * XD + dx;
    return ((msk & req) == req) ? __ldg(&g_grid[lin + koff]) : -1;
}

__device__ __forceinline__ int probe2(int k, int lin, int msk) {
    int jz = k / 9, jy = (k / 3) % 3, jx = k % 3;
    int req = ((jy == 0) ? 1 : 0) | ((jx == 0) ? 2 : 0) | ROWVALID;
    int koff = (jz * YD + jy) * XD + jx;
    return ((msk & req) == req) ? __ldg(&g_grid[lin + koff]) : -1;
}

// ---------------------------------------------------------------------------
// Rulebook builds: one thread per row; 27 independent probes (full MLP),
// then compact k-ascending entries (k<<19 | irow) into slot-major g_rb.
// ---------------------------------------------------------------------------
__global__ void rb1_build_kernel(const int* __restrict__ coors, int n) {
    int row = blockIdx.x * blockDim.x + threadIdx.x;
    if (row >= n) return;
    int4 c = ((const int4*)coors)[row];
    int lin = ((c.x * ZD + c.y) * YD + c.z) * XD + c.w;
    int msk = (c.y > 0)             |
              ((c.y < ZD - 1) << 1) |
              ((c.z > 0)      << 2) |
              ((c.z < YD - 1) << 3) |
              ((c.w > 0)      << 4) |
              ((c.w < XD - 1) << 5) |
              ROWVALID;
    int idx[27];
    #pragma unroll
    for (int k = 0; k < 27; k++) idx[k] = probe1(k, lin, msk);
    int cnt = 0;
    #pragma unroll
    for (int k = 0; k < 27; k++) {
        if (idx[k] >= 0) g_rb[(cnt++) * NMAX + row] = ((unsigned)k << 19) | (unsigned)idx[k];
    }
    g_cnt[row] = cnt;
}

__global__ void rb2_build_kernel(const int* __restrict__ ocoors, int m) {
    int row = blockIdx.x * blockDim.x + threadIdx.x;
    if (row >= m) return;
    int4 c = ((const int4*)ocoors)[row];  // (b, oz, oy, ox)
    int z0 = c.y * 2;
    int y0 = c.z * 2 - 1;
    int x0 = c.w * 2 - 1;
    int lin = ((c.x * ZD + z0) * YD + y0) * XD + x0;   // may be < 0; probes guard
    int msk = (c.z > 0) | ((c.w > 0) << 1) | ROWVALID;
    int idx[27];
    #pragma unroll
    for (int k = 0; k < 27; k++) idx[k] = probe2(k, lin, msk);
    int cnt = 0;
    #pragma unroll
    for (int k = 0; k < 27; k++) {
        if (idx[k] >= 0) g_rb[(cnt++) * NMAX + row] = ((unsigned)k << 19) | (unsigned)idx[k];
    }
    g_cnt[row] = cnt;
}

extern __shared__ float smw[];

// ---------------------------------------------------------------------------
// Layer 1: SubMConv3d CIN=16 -> C1=32, fused BN+ReLU.
// 256 thr = 8 warps, 2 blocks/SM. Warp owns 32 rows (one per lane), lane=cout.
// k-outer merge over rulebook entries; per-k register weights.
// ---------------------------------------------------------------------------
__global__ __launch_bounds__(256, 2) void conv1_kernel(
    const float* __restrict__ feat, const float* __restrict__ W1,
    const float* __restrict__ g1, const float* __restrict__ b1,
    const float* __restrict__ m1, const float* __restrict__ v1,
    int n)
{
    for (int e = threadIdx.x; e < 27 * CIN * C1; e += blockDim.x) {
        int k   = e / (CIN * C1);
        int rem = e % (CIN * C1);
        int ci  = rem / C1;
        int co  = rem % C1;
        int chunk = ci >> 2, pos = ci & 3;
        int sch = chunk ^ (co & 7);
        smw[(k * 32 + co) * 32 + sch * 4 + pos] = W1[e];
    }
    __syncthreads();

    int warp = threadIdx.x >> 5;
    int lane = threadIdx.x & 31;
    int row0 = blockIdx.x * 256 + warp * 32;
    int row  = row0 + lane;           // this lane's owned row

    int cnt = (row < n) ? __ldg(&g_cnt[row]) : 0;
    int e = 0;
    unsigned cur = (cnt > 0) ? __ldg(&g_rb[row]) : SENT;
    unsigned nxt = (cnt > 1) ? __ldg(&g_rb[NMAX + row]) : SENT;

    float acc[32];
    #pragma unroll
    for (int r = 0; r < 32; r++) acc[r] = 0.f;

    const float4* feat4 = (const float4*)feat;
    int swz = (lane & 7) * 4;

    #pragma unroll 1
    for (int k = 0; k < 27; k++) {
        bool take = ((cur >> 19) == (unsigned)k);
        unsigned mask = __ballot_sync(FULLW, take);
        if (mask) {
            const float* wrow = &smw[(k * 32 + lane) * 32];
            float4 w0 = *(const float4*)&wrow[(0 * 4) ^ swz];
            float4 w1 = *(const float4*)&wrow[(1 * 4) ^ swz];
            float4 w2 = *(const float4*)&wrow[(2 * 4) ^ swz];
            float4 w3 = *(const float4*)&wrow[(3 * 4) ^ swz];
            #pragma unroll
            for (int r = 0; r < 32; r++) {
                if ((mask >> r) & 1) {   // warp-uniform
                    int idx = __shfl_sync(FULLW, (int)cur, r) & 0x7FFFF;
                    const float4* fp = &feat4[idx * 4];
                    float4 f0 = __ldg(fp + 0);
                    float4 f1 = __ldg(fp + 1);
                    float4 f2 = __ldg(fp + 2);
                    float4 f3 = __ldg(fp + 3);
                    float a = acc[r];
                    a = fmaf(f0.x, w0.x, a); a = fmaf(f0.y, w0.y, a);
                    a = fmaf(f0.z, w0.z, a); a = fmaf(f0.w, w0.w, a);
                    a = fmaf(f1.x, w1.x, a); a = fmaf(f1.y, w1.y, a);
                    a = fmaf(f1.z, w1.z, a); a = fmaf(f1.w, w1.w, a);
                    a = fmaf(f2.x, w2.x, a); a = fmaf(f2.y, w2.y, a);
                    a = fmaf(f2.z, w2.z, a); a = fmaf(f2.w, w2.w, a);
                    a = fmaf(f3.x, w3.x, a); a = fmaf(f3.y, w3.y, a);
                    a = fmaf(f3.z, w3.z, a); a = fmaf(f3.w, w3.w, a);
                    acc[r] = a;
                }
            }
        }
        if (take) {                    // advance this lane's entry stream
            e++;
            cur = nxt;
            nxt = (e + 1 < cnt) ? __ldg(&g_rb[(e + 1) * NMAX + row]) : SENT;
        }
    }

    float s  = g1[lane] * rsqrtf(v1[lane] + BN_EPS);
    float sh = b1[lane] - m1[lane] * s;
    #pragma unroll
    for (int r = 0; r < 32; r++) {
        int rr = row0 + r;
        if (rr < n) {
            float o = fmaf(acc[r], s, sh);
            g_f1[rr * C1 + lane] = o > 0.f ? o : 0.f;
        }
    }
}

// ---------------------------------------------------------------------------
// Layer 2: SparseConv3d C1=32 -> C2=64, fused BN+ReLU.
// Cout halves split ACROSS BLOCKS (smem 110.6KB -> 2 blocks/SM).
// 256 thr = 8 warps; warp owns 32 rows (one per lane), lane = local cout.
// k-outer merge over rulebook entries; per-k 8 float4 register weights.
// ---------------------------------------------------------------------------
__global__ __launch_bounds__(256, 2) void conv2_kernel(
    const float* __restrict__ W2,
    const float* __restrict__ g2, const float* __restrict__ b2,
    const float* __restrict__ m2, const float* __restrict__ v2,
    float* __restrict__ out, int m)
{
    int half = blockIdx.x & 1;

    for (int e = threadIdx.x; e < 27 * C1 * 32; e += blockDim.x) {
        int k   = e / (C1 * 32);
        int rem = e % (C1 * 32);
        int ci  = rem / 32;
        int col = rem % 32;
        int chunk = ci >> 2, pos = ci & 3;
        int sch = chunk ^ (col & 7);
        smw[(k * 32 + col) * 32 + sch * 4 + pos] =
            W2[(k * C1 + ci) * C2 + half * 32 + col];
    }
    __syncthreads();

    int warp = threadIdx.x >> 5;
    int lane = threadIdx.x & 31;
    int row0 = (blockIdx.x >> 1) * 256 + warp * 32;
    int row  = row0 + lane;

    int cnt = (row < m) ? __ldg(&g_cnt[row]) : 0;
    int e = 0;
    unsigned cur = (cnt > 0) ? __ldg(&g_rb[row]) : SENT;
    unsigned nxt = (cnt > 1) ? __ldg(&g_rb[NMAX + row]) : SENT;

    float acc[32];
    #pragma unroll
    for (int r = 0; r < 32; r++) acc[r] = 0.f;

    const float4* f14 = (const float4*)g_f1;
    int swz = (lane & 7) * 4;

    #pragma unroll 1
    for (int k = 0; k < 27; k++) {
        bool take = ((cur >> 19) == (unsigned)k);
        unsigned mask = __ballot_sync(FULLW, take);
        if (mask) {
            const float* wrow = &smw[(k * 32 + lane) * 32];
            float4 w0 = *(const float4*)&wrow[(0 * 4) ^ swz];
            float4 w1 = *(const float4*)&wrow[(1 * 4) ^ swz];
            float4 w2 = *(const float4*)&wrow[(2 * 4) ^ swz];
            float4 w3 = *(const float4*)&wrow[(3 * 4) ^ swz];
            float4 w4 = *(const float4*)&wrow[(4 * 4) ^ swz];
            float4 w5 = *(const float4*)&wrow[(5 * 4) ^ swz];
            float4 w6 = *(const float4*)&wrow[(6 * 4) ^ swz];
            float4 w7 = *(const float4*)&wrow[(7 * 4) ^ swz];
            #pragma unroll
            for (int r = 0; r < 32; r++) {
                if ((mask >> r) & 1) {   // warp-uniform
                    int idx = __shfl_sync(FULLW, (int)cur, r) & 0x7FFFF;
                    const float4* fp = &f14[idx * 8];
                    float4 f0 = __ldg(fp + 0);
                    float4 f1 = __ldg(fp + 1);
                    float4 f2 = __ldg(fp + 2);
                    float4 f3 = __ldg(fp + 3);
                    float4 f4 = __ldg(fp + 4);
                    float4 f5 = __ldg(fp + 5);
                    float4 f6 = __ldg(fp + 6);
                    float4 f7 = __ldg(fp + 7);
                    float a = acc[r];
                    a = fmaf(f0.x, w0.x, a); a = fmaf(f0.y, w0.y, a);
                    a = fmaf(f0.z, w0.z, a); a = fmaf(f0.w, w0.w, a);
                    a = fmaf(f1.x, w1.x, a); a = fmaf(f1.y, w1.y, a);
                    a = fmaf(f1.z, w1.z, a); a = fmaf(f1.w, w1.w, a);
                    a = fmaf(f2.x, w2.x, a); a = fmaf(f2.y, w2.y, a);
                    a = fmaf(f2.z, w2.z, a); a = fmaf(f2.w, w2.w, a);
                    a = fmaf(f3.x, w3.x, a); a = fmaf(f3.y, w3.y, a);
                    a = fmaf(f3.z, w3.z, a); a = fmaf(f3.w, w3.w, a);
                    a = fmaf(f4.x, w4.x, a); a = fmaf(f4.y, w4.y, a);
                    a = fmaf(f4.z, w4.z, a); a = fmaf(f4.w, w4.w, a);
                    a = fmaf(f5.x, w5.x, a); a = fmaf(f5.y, w5.y, a);
                    a = fmaf(f5.z, w5.z, a); a = fmaf(f5.w, w5.w, a);
                    a = fmaf(f6.x, w6.x, a); a = fmaf(f6.y, w6.y, a);
                    a = fmaf(f6.z, w6.z, a); a = fmaf(f6.w, w6.w, a);
                    a = fmaf(f7.x, w7.x, a); a = fmaf(f7.y, w7.y, a);
                    a = fmaf(f7.z, w7.z, a); a = fmaf(f7.w, w7.w, a);
                    acc[r] = a;
                }
            }
        }
        if (take) {
            e++;
            cur = nxt;
            nxt = (e + 1 < cnt) ? __ldg(&g_rb[(e + 1) * NMAX + row]) : SENT;
        }
    }

    int co = half * 32 + lane;
    float s  = g2[co] * rsqrtf(v2[co] + BN_EPS);
    float sh = b2[co] - m2[co] * s;
    #pragma unroll
    for (int r = 0; r < 32; r++) {
        int rr = row0 + r;
        if (rr < m) {
            float o = fmaf(acc[r], s, sh);
            out[rr * C2 + co] = o > 0.f ? o : 0.f;
        }
    }
}

// ---------------------------------------------------------------------------
// Tail: fill everything past f2 (out_coors as float, batch_size) if the
// harness flattened the full reference tuple into d_out.
// ---------------------------------------------------------------------------
__global__ void tail_kernel(const int* __restrict__ ocoors,
                            const int* __restrict__ bsz,
                            float* __restrict__ out, int m, int total)
{
    int i = blockIdx.x * blockDim.x + threadIdx.x + m * 64;
    if (i >= total) return;
    int j = i - m * 64;
    float v;
    if (j < m * 4)       v = (float)ocoors[j];
    else if (j == m * 4) v = (float)bsz[0];
    else                 v = 0.f;
    out[i] = v;
}

// ---------------------------------------------------------------------------
extern "C" void kernel_launch(void* const* d_in, const int* in_sizes, int n_in,
                              void* d_out, int out_size)
{
    const float* feat   = (const float*)d_in[0];
    const int*   coors  = (const int*)d_in[1];
    const int*   ocoors = (const int*)d_in[2];
    const float* W1     = (const float*)d_in[3];
    const float* g1     = (const float*)d_in[4];
    const float* b1     = (const float*)d_in[5];
    const float* m1     = (const float*)d_in[6];
    const float* v1     = (const float*)d_in[7];
    const float* W2     = (const float*)d_in[8];
    const float* g2     = (const float*)d_in[9];
    const float* b2     = (const float*)d_in[10];
    const float* m2     = (const float*)d_in[11];
    const float* v2     = (const float*)d_in[12];
    const int*   bsz    = (const int*)d_in[13];

    int n = in_sizes[0] / CIN;
    int m = in_sizes[2] / 4;

    fill_grid_kernel<<<(GRID_SZ / 4 + 255) / 256, 256>>>();
    scatter_kernel<<<(n + 255) / 256, 256>>>(coors, n);

    // layer 1: rulebook, then conv
    rb1_build_kernel<<<(n + 255) / 256, 256>>>(coors, n);
    int smem1 = 27 * C1 * 32 * (int)sizeof(float);   // 110,592 B
    cudaFuncSetAttribute(conv1_kernel, cudaFuncAttributeMaxDynamicSharedMemorySize, smem1);
    conv1_kernel<<<(n + 255) / 256, 256, smem1>>>(feat, W1, g1, b1, m1, v1, n);

    // layer 2: rulebook (reuses g_rb/g_cnt), then conv
    rb2_build_kernel<<<(m + 255) / 256, 256>>>(ocoors, m);
    int smem2 = 27 * 32 * 32 * (int)sizeof(float);   // 110,592 B (half of W2)
    cudaFuncSetAttribute(conv2_kernel, cudaFuncAttributeMaxDynamicSharedMemorySize, smem2);
    int rowblocks = (m + 255) / 256;
    conv2_kernel<<<rowblocks * 2, 256, smem2>>>(W2, g2, b2, m2, v2, (float*)d_out, m);

    int tail = out_size - m * 64;
    if (tail > 0) {
        tail_kernel<<<(tail + 255) / 256, 256>>>(ocoors, bsz, (float*)d_out, m, out_size);
    }
}

// round 8
// speedup vs baseline: 1.3539x; 1.1843x over previous
#include <cuda_runtime.h>
#include <cuda_bf16.h>

#define ZD 21
#define YD 256
#define XD 256
#define CIN 16
#define C1 32
#define C2 64
#define BN_EPS 1e-3f
#define GRID_SZ (2 * ZD * YD * XD)   // 2,752,512
#define NMAX 400000
#define FULLW 0xffffffffu
#define ROWVALID 64        // mask bit: this row exists
#define SENT 0xffffffffu   // queue sentinel: k-field = 8191, never matches

__device__ int      g_grid[GRID_SZ];
__device__ float    g_f1[NMAX * C1];
__device__ unsigned g_rb[27 * NMAX];   // slot-major: rb[e*NMAX + row] (layer-2 only)
__device__ int      g_cnt[NMAX];

// ---------------------------------------------------------------------------
// Hash-grid build
// ---------------------------------------------------------------------------
__global__ void fill_grid_kernel() {
    int i = blockIdx.x * blockDim.x + threadIdx.x;
    if (i < GRID_SZ / 4) {
        ((int4*)g_grid)[i] = make_int4(-1, -1, -1, -1);
    }
}

__global__ void scatter_kernel(const int* __restrict__ coors, int n) {
    int i = blockIdx.x * blockDim.x + threadIdx.x;
    if (i < n) {
        int4 c = ((const int4*)coors)[i];  // (b, z, y, x)
        int lin = ((c.x * ZD + c.y) * YD + c.z) * XD + c.w;
        g_grid[lin] = i;
    }
}

// ---------------------------------------------------------------------------
// Probe helpers
// ---------------------------------------------------------------------------
__device__ __forceinline__ int probe2(int k, int lin, int msk) {
    int jz = k / 9, jy = (k / 3) % 3, jx = k % 3;
    int req = ((jy == 0) ? 1 : 0) | ((jx == 0) ? 2 : 0) | ROWVALID;
    int koff = (jz * YD + jy) * XD + jx;
    return ((msk & req) == req) ? __ldg(&g_grid[lin + koff]) : -1;
}

// ---------------------------------------------------------------------------
// Layer-2 rulebook: one thread per output row; 27 independent probes, then
// compact k-ascending entries (k<<19 | irow) into slot-major g_rb.
// ---------------------------------------------------------------------------
__global__ void rb2_build_kernel(const int* __restrict__ ocoors, int m) {
    int row = blockIdx.x * blockDim.x + threadIdx.x;
    if (row >= m) return;
    int4 c = ((const int4*)ocoors)[row];  // (b, oz, oy, ox)
    int z0 = c.y * 2;
    int y0 = c.z * 2 - 1;
    int x0 = c.w * 2 - 1;
    int lin = ((c.x * ZD + z0) * YD + y0) * XD + x0;   // may be < 0; probes guard
    int msk = (c.z > 0) | ((c.w > 0) << 1) | ROWVALID;
    int idx[27];
    #pragma unroll
    for (int k = 0; k < 27; k++) idx[k] = probe2(k, lin, msk);
    int cnt = 0;
    #pragma unroll
    for (int k = 0; k < 27; k++) {
        if (idx[k] >= 0) g_rb[(cnt++) * NMAX + row] = ((unsigned)k << 19) | (unsigned)idx[k];
    }
    g_cnt[row] = cnt;
}

extern __shared__ float smw[];

// ---------------------------------------------------------------------------
// Layer 1: SubMConv3d k=3 pad=1, CIN=16 -> C1=32, fused BN+ReLU
// (Round-4 structure — measured best.) 512 thr = 16 warps, 2 blocks/SM.
// Warp owns 16 rows, lane = cout; k-outer, per-k register weights,
// depth-1 probe prefetch, statically-unrolled masked inner loop.
// ---------------------------------------------------------------------------
__global__ __launch_bounds__(512, 2) void conv1_kernel(
    const float* __restrict__ feat, const int* __restrict__ coors,
    const float* __restrict__ W1,
    const float* __restrict__ g1, const float* __restrict__ b1,
    const float* __restrict__ m1, const float* __restrict__ v1,
    int n)
{
    // Stage W1[k][ci][co] -> smw[(k*32+co)*32 + (chunk^(co&7))*4 + pos], chunk=ci/4
    for (int e = threadIdx.x; e < 27 * CIN * C1; e += blockDim.x) {
        int k   = e / (CIN * C1);
        int rem = e % (CIN * C1);
        int ci  = rem / C1;
        int co  = rem % C1;
        int chunk = ci >> 2, pos = ci & 3;
        int sch = chunk ^ (co & 7);
        smw[(k * 32 + co) * 32 + sch * 4 + pos] = W1[e];
    }
    __syncthreads();

    int warp = threadIdx.x >> 5;
    int lane = threadIdx.x & 31;
    int row0 = blockIdx.x * 256 + warp * 16;

    int lin = 0, msk = 0;
    if (lane < 16) {
        int r = row0 + lane;
        if (r < n) {
            int4 c = ((const int4*)coors)[r];  // (b, z, y, x)
            lin = ((c.x * ZD + c.y) * YD + c.z) * XD + c.w;
            msk = (c.y > 0)             |
                  ((c.y < ZD - 1) << 1) |
                  ((c.z > 0)      << 2) |
                  ((c.z < YD - 1) << 3) |
                  ((c.w > 0)      << 4) |
                  ((c.w < XD - 1) << 5) |
                  ROWVALID;
        }
    }

    float acc[16];
    #pragma unroll
    for (int r = 0; r < 16; r++) acc[r] = 0.f;

    const float4* feat4 = (const float4*)feat;
    int swz = (lane & 7) * 4;

    // inline probe for k given (dz,dy,dx)
    int cur;
    {
        int req = 1 | 4 | 16 | ROWVALID;              // k=0: dz,dy,dx = -1
        int koff = (-1 * YD - 1) * XD - 1;
        cur = ((msk & req) == req) ? __ldg(&g_grid[lin + koff]) : -1;
    }
    int k = 0;
    #pragma unroll 1
    for (int dz = -1; dz <= 1; dz++) {
        #pragma unroll 1
        for (int dy = -1; dy <= 1; dy++) {
            #pragma unroll 1
            for (int dx = -1; dx <= 1; dx++, k++) {
                // prefetch k+1 probe
                int nxt = -1;
                if (k < 26) {
                    int k1 = k + 1;
                    int dz1 = k1 / 9 - 1, dy1 = (k1 / 3) % 3 - 1, dx1 = k1 % 3 - 1;
                    int req1 = ((dz1 < 0) ? 1 : 0) | ((dz1 > 0) ? 2 : 0) |
                               ((dy1 < 0) ? 4 : 0) | ((dy1 > 0) ? 8 : 0) |
                               ((dx1 < 0) ? 16 : 0) | ((dx1 > 0) ? 32 : 0) | ROWVALID;
                    int koff1 = (dz1 * YD + dy1) * XD + dx1;
                    nxt = ((msk & req1) == req1) ? __ldg(&g_grid[lin + koff1]) : -1;
                }
                unsigned mask = __ballot_sync(FULLW, cur >= 0) & 0xffffu;
                if (mask) {
                    const float* wrow = &smw[(k * 32 + lane) * 32];
                    float4 w0 = *(const float4*)&wrow[(0 * 4) ^ swz];
                    float4 w1 = *(const float4*)&wrow[(1 * 4) ^ swz];
                    float4 w2 = *(const float4*)&wrow[(2 * 4) ^ swz];
                    float4 w3 = *(const float4*)&wrow[(3 * 4) ^ swz];
                    #pragma unroll
                    for (int r = 0; r < 16; r++) {
                        if ((mask >> r) & 1) {   // warp-uniform
                            int idx = __shfl_sync(FULLW, cur, r);
                            const float4* fp = &feat4[idx * 4];
                            float4 f0 = __ldg(fp + 0);
                            float4 f1 = __ldg(fp + 1);
                            float4 f2 = __ldg(fp + 2);
                            float4 f3 = __ldg(fp + 3);
                            float a = acc[r];
                            a = fmaf(f0.x, w0.x, a); a = fmaf(f0.y, w0.y, a);
                            a = fmaf(f0.z, w0.z, a); a = fmaf(f0.w, w0.w, a);
                            a = fmaf(f1.x, w1.x, a); a = fmaf(f1.y, w1.y, a);
                            a = fmaf(f1.z, w1.z, a); a = fmaf(f1.w, w1.w, a);
                            a = fmaf(f2.x, w2.x, a); a = fmaf(f2.y, w2.y, a);
                            a = fmaf(f2.z, w2.z, a); a = fmaf(f2.w, w2.w, a);
                            a = fmaf(f3.x, w3.x, a); a = fmaf(f3.y, w3.y, a);
                            a = fmaf(f3.z, w3.z, a); a = fmaf(f3.w, w3.w, a);
                            acc[r] = a;
                        }
                    }
                }
                cur = nxt;
            }
        }
    }

    float s  = g1[lane] * rsqrtf(v1[lane] + BN_EPS);
    float sh = b1[lane] - m1[lane] * s;
    #pragma unroll
    for (int r = 0; r < 16; r++) {
        int row = row0 + r;
        if (row < n) {
            float o = fmaf(acc[r], s, sh);
            g_f1[row * C1 + lane] = o > 0.f ? o : 0.f;
        }
    }
}

// ---------------------------------------------------------------------------
// Layer 2: SparseConv3d C1=32 -> C2=64, fused BN+ReLU.
// Cout halves split ACROSS BLOCKS (smem 110.6KB -> 2 blocks/SM).
// 256 thr = 8 warps; warp owns 32 rows (one per lane), lane = local cout.
// Rulebook with 8-DEEP PRELOADED entry queue per lane: the 8 head entries are
// loaded with independent LDGs up front; consume via static shift-register.
// Lazy refill of q7 (rows with cnt>8, ~1.5%) has 7 entries of slack.
// ---------------------------------------------------------------------------
__global__ __launch_bounds__(256, 2) void conv2_kernel(
    const float* __restrict__ W2,
    const float* __restrict__ g2, const float* __restrict__ b2,
    const float* __restrict__ m2, const float* __restrict__ v2,
    float* __restrict__ out, int m)
{
    int half = blockIdx.x & 1;

    for (int e = threadIdx.x; e < 27 * C1 * 32; e += blockDim.x) {
        int k   = e / (C1 * 32);
        int rem = e % (C1 * 32);
        int ci  = rem / 32;
        int col = rem % 32;
        int chunk = ci >> 2, pos = ci & 3;
        int sch = chunk ^ (col & 7);
        smw[(k * 32 + col) * 32 + sch * 4 + pos] =
            W2[(k * C1 + ci) * C2 + half * 32 + col];
    }
    __syncthreads();

    int warp = threadIdx.x >> 5;
    int lane = threadIdx.x & 31;
    int row0 = (blockIdx.x >> 1) * 256 + warp * 32;
    int row  = row0 + lane;

    int cnt = (row < m) ? __ldg(&g_cnt[row]) : 0;
    // 8 independent preloads (no chain)
    unsigned q0 = (cnt > 0) ? __ldg(&g_rb[0 * NMAX + row]) : SENT;
    unsigned q1 = (cnt > 1) ? __ldg(&g_rb[1 * NMAX + row]) : SENT;
    unsigned q2 = (cnt > 2) ? __ldg(&g_rb[2 * NMAX + row]) : SENT;
    unsigned q3 = (cnt > 3) ? __ldg(&g_rb[3 * NMAX + row]) : SENT;
    unsigned q4 = (cnt > 4) ? __ldg(&g_rb[4 * NMAX + row]) : SENT;
    unsigned q5 = (cnt > 5) ? __ldg(&g_rb[5 * NMAX + row]) : SENT;
    unsigned q6 = (cnt > 6) ? __ldg(&g_rb[6 * NMAX + row]) : SENT;
    unsigned q7 = (cnt > 7) ? __ldg(&g_rb[7 * NMAX + row]) : SENT;
    int e = 8;   // next slot to (lazily) load

    float acc[32];
    #pragma unroll
    for (int r = 0; r < 32; r++) acc[r] = 0.f;

    const float4* f14 = (const float4*)g_f1;
    int swz = (lane & 7) * 4;

    #pragma unroll 1
    for (int k = 0; k < 27; k++) {
        bool take = ((q0 >> 19) == (unsigned)k);
        unsigned mask = __ballot_sync(FULLW, take);
        if (mask) {
            const float* wrow = &smw[(k * 32 + lane) * 32];
            float4 w0 = *(const float4*)&wrow[(0 * 4) ^ swz];
            float4 w1 = *(const float4*)&wrow[(1 * 4) ^ swz];
            float4 w2 = *(const float4*)&wrow[(2 * 4) ^ swz];
            float4 w3 = *(const float4*)&wrow[(3 * 4) ^ swz];
            float4 w4 = *(const float4*)&wrow[(4 * 4) ^ swz];
            float4 w5 = *(const float4*)&wrow[(5 * 4) ^ swz];
            float4 w6 = *(const float4*)&wrow[(6 * 4) ^ swz];
            float4 w7 = *(const float4*)&wrow[(7 * 4) ^ swz];
            #pragma unroll
            for (int r = 0; r < 32; r++) {
                if ((mask >> r) & 1) {   // warp-uniform
                    int idx = __shfl_sync(FULLW, (int)q0, r) & 0x7FFFF;
                    const float4* fp = &f14[idx * 8];
                    float4 f0 = __ldg(fp + 0);
                    float4 f1 = __ldg(fp + 1);
                    float4 f2 = __ldg(fp + 2);
                    float4 f3 = __ldg(fp + 3);
                    float4 f4 = __ldg(fp + 4);
                    float4 f5 = __ldg(fp + 5);
                    float4 f6 = __ldg(fp + 6);
                    float4 f7 = __ldg(fp + 7);
                    float a = acc[r];
                    a = fmaf(f0.x, w0.x, a); a = fmaf(f0.y, w0.y, a);
                    a = fmaf(f0.z, w0.z, a); a = fmaf(f0.w, w0.w, a);
                    a = fmaf(f1.x, w1.x, a); a = fmaf(f1.y, w1.y, a);
                    a = fmaf(f1.z, w1.z, a); a = fmaf(f1.w, w1.w, a);
                    a = fmaf(f2.x, w2.x, a); a = fmaf(f2.y, w2.y, a);
                    a = fmaf(f2.z, w2.z, a); a = fmaf(f2.w, w2.w, a);
                    a = fmaf(f3.x, w3.x, a); a = fmaf(f3.y, w3.y, a);
                    a = fmaf(f3.z, w3.z, a); a = fmaf(f3.w, w3.w, a);
                    a = fmaf(f4.x, w4.x, a); a = fmaf(f4.y, w4.y, a);
                    a = fmaf(f4.z, w4.z, a); a = fmaf(f4.w, w4.w, a);
                    a = fmaf(f5.x, w5.x, a); a = fmaf(f5.y, w5.y, a);
                    a = fmaf(f5.z, w5.z, a); a = fmaf(f5.w, w5.w, a);
                    a = fmaf(f6.x, w6.x, a); a = fmaf(f6.y, w6.y, a);
                    a = fmaf(f6.z, w6.z, a); a = fmaf(f6.w, w6.w, a);
                    a = fmaf(f7.x, w7.x, a); a = fmaf(f7.y, w7.y, a);
                    a = fmaf(f7.z, w7.z, a); a = fmaf(f7.w, w7.w, a);
                    acc[r] = a;
                }
            }
        }
        if (take) {   // static shift-register consume; lazy tail refill
            q0 = q1; q1 = q2; q2 = q3; q3 = q4;
            q4 = q5; q5 = q6; q6 = q7;
            q7 = (e < cnt) ? __ldg(&g_rb[e * NMAX + row]) : SENT;
            e++;
        }
    }

    int co = half * 32 + lane;
    float s  = g2[co] * rsqrtf(v2[co] + BN_EPS);
    float sh = b2[co] - m2[co] * s;
    #pragma unroll
    for (int r = 0; r < 32; r++) {
        int rr = row0 + r;
        if (rr < m) {
            float o = fmaf(acc[r], s, sh);
            out[rr * C2 + co] = o > 0.f ? o : 0.f;
        }
    }
}

// ---------------------------------------------------------------------------
// Tail: fill everything past f2 (out_coors as float, batch_size) if the
// harness flattened the full reference tuple into d_out.
// ---------------------------------------------------------------------------
__global__ void tail_kernel(const int* __restrict__ ocoors,
                            const int* __restrict__ bsz,
                            float* __restrict__ out, int m, int total)
{
    int i = blockIdx.x * blockDim.x + threadIdx.x + m * 64;
    if (i >= total) return;
    int j = i - m * 64;
    float v;
    if (j < m * 4)       v = (float)ocoors[j];
    else if (j == m * 4) v = (float)bsz[0];
    else                 v = 0.f;
    out[i] = v;
}

// ---------------------------------------------------------------------------
extern "C" void kernel_launch(void* const* d_in, const int* in_sizes, int n_in,
                              void* d_out, int out_size)
{
    const float* feat   = (const float*)d_in[0];
    const int*   coors  = (const int*)d_in[1];
    const int*   ocoors = (const int*)d_in[2];
    const float* W1     = (const float*)d_in[3];
    const float* g1     = (const float*)d_in[4];
    const float* b1     = (const float*)d_in[5];
    const float* m1     = (const float*)d_in[6];
    const float* v1     = (const float*)d_in[7];
    const float* W2     = (const float*)d_in[8];
    const float* g2     = (const float*)d_in[9];
    const float* b2     = (const float*)d_in[10];
    const float* m2     = (const float*)d_in[11];
    const float* v2     = (const float*)d_in[12];
    const int*   bsz    = (const int*)d_in[13];

    int n = in_sizes[0] / CIN;
    int m = in_sizes[2] / 4;

    fill_grid_kernel<<<(GRID_SZ / 4 + 255) / 256, 256>>>();
    scatter_kernel<<<(n + 255) / 256, 256>>>(coors, n);

    // layer 1 (inline probes, no rulebook)
    int smem1 = 27 * C1 * 32 * (int)sizeof(float);   // 110,592 B
    cudaFuncSetAttribute(conv1_kernel, cudaFuncAttributeMaxDynamicSharedMemorySize, smem1);
    conv1_kernel<<<(n + 255) / 256, 512, smem1>>>(feat, coors, W1, g1, b1, m1, v1, n);

    // layer 2: rulebook, then conv with preloaded entry queues
    rb2_build_kernel<<<(m + 255) / 256, 256>>>(ocoors, m);
    int smem2 = 27 * 32 * 32 * (int)sizeof(float);   // 110,592 B (half of W2)
    cudaFuncSetAttribute(conv2_kernel, cudaFuncAttributeMaxDynamicSharedMemorySize, smem2);
    int rowblocks = (m + 255) / 256;
    conv2_kernel<<<rowblocks * 2, 256, smem2>>>(W2, g2, b2, m2, v2, (float*)d_out, m);

    int tail = out_size - m * 64;
    if (tail > 0) {
        tail_kernel<<<(tail + 255) / 256, 256>>>(ocoors, bsz, (float*)d_out, m, out_size);
    }
}

// round 9
// speedup vs baseline: 1.3957x; 1.0309x over previous
#include <cuda_runtime.h>
#include <cuda_bf16.h>

#define ZD 21
#define YD 256
#define XD 256
#define CIN 16
#define C1 32
#define C2 64
#define BN_EPS 1e-3f
#define GRID_SZ (2 * ZD * YD * XD)   // 2,752,512
#define NMAX 400000
#define FULLW 0xffffffffu
#define ROWVALID 64        // mask bit: this row exists
#define SENT 0xffffffffu   // queue sentinel: k-field = 8191, never matches

__device__ int      g_grid[GRID_SZ];
__device__ float    g_f1[NMAX * C1];
__device__ unsigned g_rb[27 * NMAX];   // slot-major: rb[e*NMAX + row] (layer-2 only)
__device__ int      g_cnt[NMAX];

__device__ __forceinline__ void prefetchL1(const void* p) {
    asm volatile("prefetch.global.L1 [%0];" :: "l"(p));
}

// ---------------------------------------------------------------------------
// Hash-grid build
// ---------------------------------------------------------------------------
__global__ void fill_grid_kernel() {
    int i = blockIdx.x * blockDim.x + threadIdx.x;
    if (i < GRID_SZ / 4) {
        ((int4*)g_grid)[i] = make_int4(-1, -1, -1, -1);
    }
}

__global__ void scatter_kernel(const int* __restrict__ coors, int n) {
    int i = blockIdx.x * blockDim.x + threadIdx.x;
    if (i < n) {
        int4 c = ((const int4*)coors)[i];  // (b, z, y, x)
        int lin = ((c.x * ZD + c.y) * YD + c.z) * XD + c.w;
        g_grid[lin] = i;
    }
}

// ---------------------------------------------------------------------------
// Probe helpers
// ---------------------------------------------------------------------------
__device__ __forceinline__ int probe2(int k, int lin, int msk) {
    int jz = k / 9, jy = (k / 3) % 3, jx = k % 3;
    int req = ((jy == 0) ? 1 : 0) | ((jx == 0) ? 2 : 0) | ROWVALID;
    int koff = (jz * YD + jy) * XD + jx;
    return ((msk & req) == req) ? __ldg(&g_grid[lin + koff]) : -1;
}

// ---------------------------------------------------------------------------
// Layer-2 rulebook: one thread per output row; 27 independent probes, then
// compact k-ascending entries (k<<19 | irow) into slot-major g_rb.
// ---------------------------------------------------------------------------
__global__ void rb2_build_kernel(const int* __restrict__ ocoors, int m) {
    int row = blockIdx.x * blockDim.x + threadIdx.x;
    if (row >= m) return;
    int4 c = ((const int4*)ocoors)[row];  // (b, oz, oy, ox)
    int z0 = c.y * 2;
    int y0 = c.z * 2 - 1;
    int x0 = c.w * 2 - 1;
    int lin = ((c.x * ZD + z0) * YD + y0) * XD + x0;   // may be < 0; probes guard
    int msk = (c.z > 0) | ((c.w > 0) << 1) | ROWVALID;
    int idx[27];
    #pragma unroll
    for (int k = 0; k < 27; k++) idx[k] = probe2(k, lin, msk);
    int cnt = 0;
    #pragma unroll
    for (int k = 0; k < 27; k++) {
        if (idx[k] >= 0) g_rb[(cnt++) * NMAX + row] = ((unsigned)k << 19) | (unsigned)idx[k];
    }
    g_cnt[row] = cnt;
}

extern __shared__ float smw[];

// ---------------------------------------------------------------------------
// Layer 1: SubMConv3d k=3 pad=1, CIN=16 -> C1=32, fused BN+ReLU
// 512 thr = 16 warps, 2 blocks/SM. Warp owns 16 rows, lane = cout; k-outer,
// per-k register weights, depth-1 probe prefetch + L1 feature-line prefetch.
// ---------------------------------------------------------------------------
__global__ __launch_bounds__(512, 2) void conv1_kernel(
    const float* __restrict__ feat, const int* __restrict__ coors,
    const float* __restrict__ W1,
    const float* __restrict__ g1, const float* __restrict__ b1,
    const float* __restrict__ m1, const float* __restrict__ v1,
    int n)
{
    // Stage W1[k][ci][co] -> smw[(k*32+co)*32 + (chunk^(co&7))*4 + pos], chunk=ci/4
    for (int e = threadIdx.x; e < 27 * CIN * C1; e += blockDim.x) {
        int k   = e / (CIN * C1);
        int rem = e % (CIN * C1);
        int ci  = rem / C1;
        int co  = rem % C1;
        int chunk = ci >> 2, pos = ci & 3;
        int sch = chunk ^ (co & 7);
        smw[(k * 32 + co) * 32 + sch * 4 + pos] = W1[e];
    }
    __syncthreads();

    int warp = threadIdx.x >> 5;
    int lane = threadIdx.x & 31;
    int row0 = blockIdx.x * 256 + warp * 16;

    int lin = 0, msk = 0;
    if (lane < 16) {
        int r = row0 + lane;
        if (r < n) {
            int4 c = ((const int4*)coors)[r];  // (b, z, y, x)
            lin = ((c.x * ZD + c.y) * YD + c.z) * XD + c.w;
            msk = (c.y > 0)             |
                  ((c.y < ZD - 1) << 1) |
                  ((c.z > 0)      << 2) |
                  ((c.z < YD - 1) << 3) |
                  ((c.w > 0)      << 4) |
                  ((c.w < XD - 1) << 5) |
                  ROWVALID;
        }
    }

    float acc[16];
    #pragma unroll
    for (int r = 0; r < 16; r++) acc[r] = 0.f;

    const float4* feat4 = (const float4*)feat;
    int swz = (lane & 7) * 4;

    // inline probe for k=0
    int cur;
    {
        int req = 1 | 4 | 16 | ROWVALID;              // k=0: dz,dy,dx = -1
        int koff = (-1 * YD - 1) * XD - 1;
        cur = ((msk & req) == req) ? __ldg(&g_grid[lin + koff]) : -1;
        if (cur >= 0) prefetchL1(&feat4[cur * 4]);    // warm L1 for k=0's gather
    }
    int k = 0;
    #pragma unroll 1
    for (int dz = -1; dz <= 1; dz++) {
        #pragma unroll 1
        for (int dy = -1; dy <= 1; dy++) {
            #pragma unroll 1
            for (int dx = -1; dx <= 1; dx++, k++) {
                // prefetch k+1 probe and its feature line
                int nxt = -1;
                if (k < 26) {
                    int k1 = k + 1;
                    int dz1 = k1 / 9 - 1, dy1 = (k1 / 3) % 3 - 1, dx1 = k1 % 3 - 1;
                    int req1 = ((dz1 < 0) ? 1 : 0) | ((dz1 > 0) ? 2 : 0) |
                               ((dy1 < 0) ? 4 : 0) | ((dy1 > 0) ? 8 : 0) |
                               ((dx1 < 0) ? 16 : 0) | ((dx1 > 0) ? 32 : 0) | ROWVALID;
                    int koff1 = (dz1 * YD + dy1) * XD + dx1;
                    nxt = ((msk & req1) == req1) ? __ldg(&g_grid[lin + koff1]) : -1;
                    if (nxt >= 0) prefetchL1(&feat4[nxt * 4]);
                }
                unsigned mask = __ballot_sync(FULLW, cur >= 0) & 0xffffu;
                if (mask) {
                    const float* wrow = &smw[(k * 32 + lane) * 32];
                    float4 w0 = *(const float4*)&wrow[(0 * 4) ^ swz];
                    float4 w1 = *(const float4*)&wrow[(1 * 4) ^ swz];
                    float4 w2 = *(const float4*)&wrow[(2 * 4) ^ swz];
                    float4 w3 = *(const float4*)&wrow[(3 * 4) ^ swz];
                    #pragma unroll
                    for (int r = 0; r < 16; r++) {
                        if ((mask >> r) & 1) {   // warp-uniform
                            int idx = __shfl_sync(FULLW, cur, r);
                            const float4* fp = &feat4[idx * 4];
                            float4 f0 = __ldg(fp + 0);
                            float4 f1 = __ldg(fp + 1);
                            float4 f2 = __ldg(fp + 2);
                            float4 f3 = __ldg(fp + 3);
                            float a = acc[r];
                            a = fmaf(f0.x, w0.x, a); a = fmaf(f0.y, w0.y, a);
                            a = fmaf(f0.z, w0.z, a); a = fmaf(f0.w, w0.w, a);
                            a = fmaf(f1.x, w1.x, a); a = fmaf(f1.y, w1.y, a);
                            a = fmaf(f1.z, w1.z, a); a = fmaf(f1.w, w1.w, a);
                            a = fmaf(f2.x, w2.x, a); a = fmaf(f2.y, w2.y, a);
                            a = fmaf(f2.z, w2.z, a); a = fmaf(f2.w, w2.w, a);
                            a = fmaf(f3.x, w3.x, a); a = fmaf(f3.y, w3.y, a);
                            a = fmaf(f3.z, w3.z, a); a = fmaf(f3.w, w3.w, a);
                            acc[r] = a;
                        }
                    }
                }
                cur = nxt;
            }
        }
    }

    float s  = g1[lane] * rsqrtf(v1[lane] + BN_EPS);
    float sh = b1[lane] - m1[lane] * s;
    #pragma unroll
    for (int r = 0; r < 16; r++) {
        int row = row0 + r;
        if (row < n) {
            float o = fmaf(acc[r], s, sh);
            g_f1[row * C1 + lane] = o > 0.f ? o : 0.f;
        }
    }
}

// ---------------------------------------------------------------------------
// Layer 2: SparseConv3d C1=32 -> C2=64, fused BN+ReLU.
// Cout halves split ACROSS BLOCKS (smem 110.6KB -> 2 blocks/SM).
// 256 thr = 8 warps; warp owns 32 rows (one per lane), lane = local cout.
// 8-deep preloaded entry queue per lane + L1 prefetch of the feature lines
// for the two queue-head entries (each g_f1 row = one 128B L1 line).
// ---------------------------------------------------------------------------
__global__ __launch_bounds__(256, 2) void conv2_kernel(
    const float* __restrict__ W2,
    const float* __restrict__ g2, const float* __restrict__ b2,
    const float* __restrict__ m2, const float* __restrict__ v2,
    float* __restrict__ out, int m)
{
    int half = blockIdx.x & 1;

    for (int e = threadIdx.x; e < 27 * C1 * 32; e += blockDim.x) {
        int k   = e / (C1 * 32);
        int rem = e % (C1 * 32);
        int ci  = rem / 32;
        int col = rem % 32;
        int chunk = ci >> 2, pos = ci & 3;
        int sch = chunk ^ (col & 7);
        smw[(k * 32 + col) * 32 + sch * 4 + pos] =
            W2[(k * C1 + ci) * C2 + half * 32 + col];
    }
    __syncthreads();

    int warp = threadIdx.x >> 5;
    int lane = threadIdx.x & 31;
    int row0 = (blockIdx.x >> 1) * 256 + warp * 32;
    int row  = row0 + lane;

    const float4* f14 = (const float4*)g_f1;

    int cnt = (row < m) ? __ldg(&g_cnt[row]) : 0;
    // 8 independent preloads (no chain)
    unsigned q0 = (cnt > 0) ? __ldg(&g_rb[0 * NMAX + row]) : SENT;
    unsigned q1 = (cnt > 1) ? __ldg(&g_rb[1 * NMAX + row]) : SENT;
    unsigned q2 = (cnt > 2) ? __ldg(&g_rb[2 * NMAX + row]) : SENT;
    unsigned q3 = (cnt > 3) ? __ldg(&g_rb[3 * NMAX + row]) : SENT;
    unsigned q4 = (cnt > 4) ? __ldg(&g_rb[4 * NMAX + row]) : SENT;
    unsigned q5 = (cnt > 5) ? __ldg(&g_rb[5 * NMAX + row]) : SENT;
    unsigned q6 = (cnt > 6) ? __ldg(&g_rb[6 * NMAX + row]) : SENT;
    unsigned q7 = (cnt > 7) ? __ldg(&g_rb[7 * NMAX + row]) : SENT;
    int e = 8;   // next slot to (lazily) load

    // warm L1 with the first two entries' feature lines (one line per row)
    if (q0 != SENT) prefetchL1(&f14[(q0 & 0x7FFFF) * 8]);
    if (q1 != SENT) prefetchL1(&f14[(q1 & 0x7FFFF) * 8]);

    float acc[32];
    #pragma unroll
    for (int r = 0; r < 32; r++) acc[r] = 0.f;

    int swz = (lane & 7) * 4;

    #pragma unroll 1
    for (int k = 0; k < 27; k++) {
        bool take = ((q0 >> 19) == (unsigned)k);
        unsigned mask = __ballot_sync(FULLW, take);
        if (mask) {
            const float* wrow = &smw[(k * 32 + lane) * 32];
            float4 w0 = *(const float4*)&wrow[(0 * 4) ^ swz];
            float4 w1 = *(const float4*)&wrow[(1 * 4) ^ swz];
            float4 w2 = *(const float4*)&wrow[(2 * 4) ^ swz];
            float4 w3 = *(const float4*)&wrow[(3 * 4) ^ swz];
            float4 w4 = *(const float4*)&wrow[(4 * 4) ^ swz];
            float4 w5 = *(const float4*)&wrow[(5 * 4) ^ swz];
            float4 w6 = *(const float4*)&wrow[(6 * 4) ^ swz];
            float4 w7 = *(const float4*)&wrow[(7 * 4) ^ swz];
            #pragma unroll
            for (int r = 0; r < 32; r++) {
                if ((mask >> r) & 1) {   // warp-uniform
                    int idx = __shfl_sync(FULLW, (int)q0, r) & 0x7FFFF;
                    const float4* fp = &f14[idx * 8];
                    float4 f0 = __ldg(fp + 0);
                    float4 f1 = __ldg(fp + 1);
                    float4 f2 = __ldg(fp + 2);
                    float4 f3 = __ldg(fp + 3);
                    float4 f4 = __ldg(fp + 4);
                    float4 f5 = __ldg(fp + 5);
                    float4 f6 = __ldg(fp + 6);
                    float4 f7 = __ldg(fp + 7);
                    float a = acc[r];
                    a = fmaf(f0.x, w0.x, a); a = fmaf(f0.y, w0.y, a);
                    a = fmaf(f0.z, w0.z, a); a = fmaf(f0.w, w0.w, a);
                    a = fmaf(f1.x, w1.x, a); a = fmaf(f1.y, w1.y, a);
                    a = fmaf(f1.z, w1.z, a); a = fmaf(f1.w, w1.w, a);
                    a = fmaf(f2.x, w2.x, a); a = fmaf(f2.y, w2.y, a);
                    a = fmaf(f2.z, w2.z, a); a = fmaf(f2.w, w2.w, a);
                    a = fmaf(f3.x, w3.x, a); a = fmaf(f3.y, w3.y, a);
                    a = fmaf(f3.z, w3.z, a); a = fmaf(f3.w, w3.w, a);
                    a = fmaf(f4.x, w4.x, a); a = fmaf(f4.y, w4.y, a);
                    a = fmaf(f4.z, w4.z, a); a = fmaf(f4.w, w4.w, a);
                    a = fmaf(f5.x, w5.x, a); a = fmaf(f5.y, w5.y, a);
                    a = fmaf(f5.z, w5.z, a); a = fmaf(f5.w, w5.w, a);
                    a = fmaf(f6.x, w6.x, a); a = fmaf(f6.y, w6.y, a);
                    a = fmaf(f6.z, w6.z, a); a = fmaf(f6.w, w6.w, a);
                    a = fmaf(f7.x, w7.x, a); a = fmaf(f7.y, w7.y, a);
                    a = fmaf(f7.z, w7.z, a); a = fmaf(f7.w, w7.w, a);
                    acc[r] = a;
                }
            }
        }
        if (take) {   // static shift-register consume; lazy tail refill
            q0 = q1; q1 = q2; q2 = q3; q3 = q4;
            q4 = q5; q5 = q6; q6 = q7;
            q7 = (e < cnt) ? __ldg(&g_rb[e * NMAX + row]) : SENT;
            e++;
            if (q1 != SENT) prefetchL1(&f14[(q1 & 0x7FFFF) * 8]);  // keep depth-2 warm
        }
    }

    int co = half * 32 + lane;
    float s  = g2[co] * rsqrtf(v2[co] + BN_EPS);
    float sh = b2[co] - m2[co] * s;
    #pragma unroll
    for (int r = 0; r < 32; r++) {
        int rr = row0 + r;
        if (rr < m) {
            float o = fmaf(acc[r], s, sh);
            out[rr * C2 + co] = o > 0.f ? o : 0.f;
        }
    }
}

// ---------------------------------------------------------------------------
// Tail: fill everything past f2 (out_coors as float, batch_size) if the
// harness flattened the full reference tuple into d_out.
// ---------------------------------------------------------------------------
__global__ void tail_kernel(const int* __restrict__ ocoors,
                            const int* __restrict__ bsz,
                            float* __restrict__ out, int m, int total)
{
    int i = blockIdx.x * blockDim.x + threadIdx.x + m * 64;
    if (i >= total) return;
    int j = i - m * 64;
    float v;
    if (j < m * 4)       v = (float)ocoors[j];
    else if (j == m * 4) v = (float)bsz[0];
    else                 v = 0.f;
    out[i] = v;
}

// ---------------------------------------------------------------------------
extern "C" void kernel_launch(void* const* d_in, const int* in_sizes, int n_in,
                              void* d_out, int out_size)
{
    const float* feat   = (const float*)d_in[0];
    const int*   coors  = (const int*)d_in[1];
    const int*   ocoors = (const int*)d_in[2];
    const float* W1     = (const float*)d_in[3];
    const float* g1     = (const float*)d_in[4];
    const float* b1     = (const float*)d_in[5];
    const float* m1     = (const float*)d_in[6];
    const float* v1     = (const float*)d_in[7];
    const float* W2     = (const float*)d_in[8];
    const float* g2     = (const float*)d_in[9];
    const float* b2     = (const float*)d_in[10];
    const float* m2     = (const float*)d_in[11];
    const float* v2     = (const float*)d_in[12];
    const int*   bsz    = (const int*)d_in[13];

    int n = in_sizes[0] / CIN;
    int m = in_sizes[2] / 4;

    fill_grid_kernel<<<(GRID_SZ / 4 + 255) / 256, 256>>>();
    scatter_kernel<<<(n + 255) / 256, 256>>>(coors, n);

    // layer 1 (inline probes, no rulebook)
    int smem1 = 27 * C1 * 32 * (int)sizeof(float);   // 110,592 B
    cudaFuncSetAttribute(conv1_kernel, cudaFuncAttributeMaxDynamicSharedMemorySize, smem1);
    conv1_kernel<<<(n + 255) / 256, 512, smem1>>>(feat, coors, W1, g1, b1, m1, v1, n);

    // layer 2: rulebook, then conv with preloaded entry queues + L1 prefetch
    rb2_build_kernel<<<(m + 255) / 256, 256>>>(ocoors, m);
    int smem2 = 27 * 32 * 32 * (int)sizeof(float);   // 110,592 B (half of W2)
    cudaFuncSetAttribute(conv2_kernel, cudaFuncAttributeMaxDynamicSharedMemorySize, smem2);
    int rowblocks = (m + 255) / 256;
    conv2_kernel<<<rowblocks * 2, 256, smem2>>>(W2, g2, b2, m2, v2, (float*)d_out, m);

    int tail = out_size - m * 64;
    if (tail > 0) {
        tail_kernel<<<(tail + 255) / 256, 256>>>(ocoors, bsz, (float*)d_out, m, out_size);
    }
}

// round 10
// speedup vs baseline: 1.6021x; 1.1479x over previous
#include <cuda_runtime.h>
#include <cuda_bf16.h>

#define ZD 21
#define YD 256
#define XD 256
#define CIN 16
#define C1 32
#define C2 64
#define BN_EPS 1e-3f
#define GRID_SZ (2 * ZD * YD * XD)   // 2,752,512
#define NMAX 400000
#define FULLW 0xffffffffu
#define ROWVALID 64        // mask bit: this row exists
#define SENT 0xffffffffu   // queue sentinel: k-field = 8191, never matches

__device__ int      g_grid[GRID_SZ];
__device__ float    g_f1[NMAX * C1];
__device__ unsigned g_rb[27 * NMAX];   // slot-major: rb[e*NMAX + row] (layer-2 only)
__device__ int      g_cnt[NMAX];

__device__ __forceinline__ void prefetchL1(const void* p) {
    asm volatile("prefetch.global.L1 [%0];" :: "l"(p));
}

// ---------------------------------------------------------------------------
// Hash-grid build
// ---------------------------------------------------------------------------
__global__ void fill_grid_kernel() {
    int i = blockIdx.x * blockDim.x + threadIdx.x;
    if (i < GRID_SZ / 4) {
        ((int4*)g_grid)[i] = make_int4(-1, -1, -1, -1);
    }
}

__global__ void scatter_kernel(const int* __restrict__ coors, int n) {
    int i = blockIdx.x * blockDim.x + threadIdx.x;
    if (i < n) {
        int4 c = ((const int4*)coors)[i];  // (b, z, y, x)
        int lin = ((c.x * ZD + c.y) * YD + c.z) * XD + c.w;
        g_grid[lin] = i;
    }
}

// ---------------------------------------------------------------------------
// Probe helpers
// ---------------------------------------------------------------------------
__device__ __forceinline__ int probe2(int k, int lin, int msk) {
    int jz = k / 9, jy = (k / 3) % 3, jx = k % 3;
    int req = ((jy == 0) ? 1 : 0) | ((jx == 0) ? 2 : 0) | ROWVALID;
    int koff = (jz * YD + jy) * XD + jx;
    return ((msk & req) == req) ? __ldg(&g_grid[lin + koff]) : -1;
}

// ---------------------------------------------------------------------------
// Layer-2 rulebook: one thread per output row; 27 independent probes, then
// compact k-ascending entries (k<<19 | irow) into slot-major g_rb.
// ---------------------------------------------------------------------------
__global__ void rb2_build_kernel(const int* __restrict__ ocoors, int m) {
    int row = blockIdx.x * blockDim.x + threadIdx.x;
    if (row >= m) return;
    int4 c = ((const int4*)ocoors)[row];  // (b, oz, oy, ox)
    int z0 = c.y * 2;
    int y0 = c.z * 2 - 1;
    int x0 = c.w * 2 - 1;
    int lin = ((c.x * ZD + z0) * YD + y0) * XD + x0;   // may be < 0; probes guard
    int msk = (c.z > 0) | ((c.w > 0) << 1) | ROWVALID;
    int idx[27];
    #pragma unroll
    for (int k = 0; k < 27; k++) idx[k] = probe2(k, lin, msk);
    int cnt = 0;
    #pragma unroll
    for (int k = 0; k < 27; k++) {
        if (idx[k] >= 0) g_rb[(cnt++) * NMAX + row] = ((unsigned)k << 19) | (unsigned)idx[k];
    }
    g_cnt[row] = cnt;
}

extern __shared__ float smw[];

// ---------------------------------------------------------------------------
// Layer 1: SubMConv3d k=3 pad=1, CIN=16 -> C1=32, fused BN+ReLU
// 512 thr = 16 warps, 2 blocks/SM. Warp owns 16 rows, lane = cout; k-outer,
// per-k register weights, depth-1 probe prefetch + L1 feature-line prefetch.
// (unchanged from 827us version)
// ---------------------------------------------------------------------------
__global__ __launch_bounds__(512, 2) void conv1_kernel(
    const float* __restrict__ feat, const int* __restrict__ coors,
    const float* __restrict__ W1,
    const float* __restrict__ g1, const float* __restrict__ b1,
    const float* __restrict__ m1, const float* __restrict__ v1,
    int n)
{
    for (int e = threadIdx.x; e < 27 * CIN * C1; e += blockDim.x) {
        int k   = e / (CIN * C1);
        int rem = e % (CIN * C1);
        int ci  = rem / C1;
        int co  = rem % C1;
        int chunk = ci >> 2, pos = ci & 3;
        int sch = chunk ^ (co & 7);
        smw[(k * 32 + co) * 32 + sch * 4 + pos] = W1[e];
    }
    __syncthreads();

    int warp = threadIdx.x >> 5;
    int lane = threadIdx.x & 31;
    int row0 = blockIdx.x * 256 + warp * 16;

    int lin = 0, msk = 0;
    if (lane < 16) {
        int r = row0 + lane;
        if (r < n) {
            int4 c = ((const int4*)coors)[r];  // (b, z, y, x)
            lin = ((c.x * ZD + c.y) * YD + c.z) * XD + c.w;
            msk = (c.y > 0)             |
                  ((c.y < ZD - 1) << 1) |
                  ((c.z > 0)      << 2) |
                  ((c.z < YD - 1) << 3) |
                  ((c.w > 0)      << 4) |
                  ((c.w < XD - 1) << 5) |
                  ROWVALID;
        }
    }

    float acc[16];
    #pragma unroll
    for (int r = 0; r < 16; r++) acc[r] = 0.f;

    const float4* feat4 = (const float4*)feat;
    int swz = (lane & 7) * 4;

    int cur;
    {
        int req = 1 | 4 | 16 | ROWVALID;              // k=0: dz,dy,dx = -1
        int koff = (-1 * YD - 1) * XD - 1;
        cur = ((msk & req) == req) ? __ldg(&g_grid[lin + koff]) : -1;
        if (cur >= 0) prefetchL1(&feat4[cur * 4]);
    }
    int k = 0;
    #pragma unroll 1
    for (int dz = -1; dz <= 1; dz++) {
        #pragma unroll 1
        for (int dy = -1; dy <= 1; dy++) {
            #pragma unroll 1
            for (int dx = -1; dx <= 1; dx++, k++) {
                int nxt = -1;
                if (k < 26) {
                    int k1 = k + 1;
                    int dz1 = k1 / 9 - 1, dy1 = (k1 / 3) % 3 - 1, dx1 = k1 % 3 - 1;
                    int req1 = ((dz1 < 0) ? 1 : 0) | ((dz1 > 0) ? 2 : 0) |
                               ((dy1 < 0) ? 4 : 0) | ((dy1 > 0) ? 8 : 0) |
                               ((dx1 < 0) ? 16 : 0) | ((dx1 > 0) ? 32 : 0) | ROWVALID;
                    int koff1 = (dz1 * YD + dy1) * XD + dx1;
                    nxt = ((msk & req1) == req1) ? __ldg(&g_grid[lin + koff1]) : -1;
                    if (nxt >= 0) prefetchL1(&feat4[nxt * 4]);
                }
                unsigned mask = __ballot_sync(FULLW, cur >= 0) & 0xffffu;
                if (mask) {
                    const float* wrow = &smw[(k * 32 + lane) * 32];
                    float4 w0 = *(const float4*)&wrow[(0 * 4) ^ swz];
                    float4 w1 = *(const float4*)&wrow[(1 * 4) ^ swz];
                    float4 w2 = *(const float4*)&wrow[(2 * 4) ^ swz];
                    float4 w3 = *(const float4*)&wrow[(3 * 4) ^ swz];
                    #pragma unroll
                    for (int r = 0; r < 16; r++) {
                        if ((mask >> r) & 1) {   // warp-uniform
                            int idx = __shfl_sync(FULLW, cur, r);
                            const float4* fp = &feat4[idx * 4];
                            float4 f0 = __ldg(fp + 0);
                            float4 f1 = __ldg(fp + 1);
                            float4 f2 = __ldg(fp + 2);
                            float4 f3 = __ldg(fp + 3);
                            float a = acc[r];
                            a = fmaf(f0.x, w0.x, a); a = fmaf(f0.y, w0.y, a);
                            a = fmaf(f0.z, w0.z, a); a = fmaf(f0.w, w0.w, a);
                            a = fmaf(f1.x, w1.x, a); a = fmaf(f1.y, w1.y, a);
                            a = fmaf(f1.z, w1.z, a); a = fmaf(f1.w, w1.w, a);
                            a = fmaf(f2.x, w2.x, a); a = fmaf(f2.y, w2.y, a);
                            a = fmaf(f2.z, w2.z, a); a = fmaf(f2.w, w2.w, a);
                            a = fmaf(f3.x, w3.x, a); a = fmaf(f3.y, w3.y, a);
                            a = fmaf(f3.z, w3.z, a); a = fmaf(f3.w, w3.w, a);
                            acc[r] = a;
                        }
                    }
                }
                cur = nxt;
            }
        }
    }

    float s  = g1[lane] * rsqrtf(v1[lane] + BN_EPS);
    float sh = b1[lane] - m1[lane] * s;
    #pragma unroll
    for (int r = 0; r < 16; r++) {
        int row = row0 + r;
        if (row < n) {
            float o = fmaf(acc[r], s, sh);
            g_f1[row * C1 + lane] = o > 0.f ? o : 0.f;
        }
    }
}

// ---------------------------------------------------------------------------
// Layer 2: SparseConv3d C1=32 -> C2=64, fused BN+ReLU.
// Cout halves split ACROSS BLOCKS. 512 thr = 16 warps, 1 block/SM
// (smem = 110.6KB weights + 64KB smem accumulators = 176KB).
// Warp owns 32 rows (one per lane); lane = local cout.
// Accumulators live in SMEM (per-thread-private slots); valid pairs are
// processed by a dynamic __ffs loop, 2-way interleaved: both pairs' feature
// loads issue before either FMA chain -> 2x chain ILP + load/chain overlap.
// ---------------------------------------------------------------------------
#define CONV2_W_ELEMS (27 * 32 * 32)

__global__ __launch_bounds__(512, 1) void conv2_kernel(
    const float* __restrict__ W2,
    const float* __restrict__ g2, const float* __restrict__ b2,
    const float* __restrict__ m2, const float* __restrict__ v2,
    float* __restrict__ out, int m)
{
    int half = blockIdx.x & 1;

    for (int e = threadIdx.x; e < CONV2_W_ELEMS; e += blockDim.x) {
        int k   = e / (C1 * 32);
        int rem = e % (C1 * 32);
        int ci  = rem / 32;
        int col = rem % 32;
        int chunk = ci >> 2, pos = ci & 3;
        int sch = chunk ^ (col & 7);
        smw[(k * 32 + col) * 32 + sch * 4 + pos] =
            W2[(k * C1 + ci) * C2 + half * 32 + col];
    }

    int warp = threadIdx.x >> 5;
    int lane = threadIdx.x & 31;

    // per-warp smem accumulator block: sacc[r*32 + lane], r = 0..31
    float* sacc = smw + CONV2_W_ELEMS + warp * (32 * 32);
    #pragma unroll
    for (int r = 0; r < 32; r++) sacc[r * 32 + lane] = 0.f;
    __syncthreads();

    int row0 = (blockIdx.x >> 1) * 512 + warp * 32;
    int row  = row0 + lane;

    const float4* f14 = (const float4*)g_f1;

    int cnt = (row < m) ? __ldg(&g_cnt[row]) : 0;
    unsigned q0 = (cnt > 0) ? __ldg(&g_rb[0 * NMAX + row]) : SENT;
    unsigned q1 = (cnt > 1) ? __ldg(&g_rb[1 * NMAX + row]) : SENT;
    unsigned q2 = (cnt > 2) ? __ldg(&g_rb[2 * NMAX + row]) : SENT;
    unsigned q3 = (cnt > 3) ? __ldg(&g_rb[3 * NMAX + row]) : SENT;
    unsigned q4 = (cnt > 4) ? __ldg(&g_rb[4 * NMAX + row]) : SENT;
    unsigned q5 = (cnt > 5) ? __ldg(&g_rb[5 * NMAX + row]) : SENT;
    unsigned q6 = (cnt > 6) ? __ldg(&g_rb[6 * NMAX + row]) : SENT;
    unsigned q7 = (cnt > 7) ? __ldg(&g_rb[7 * NMAX + row]) : SENT;
    int e = 8;

    if (q0 != SENT) prefetchL1(&f14[(q0 & 0x7FFFF) * 8]);
    if (q1 != SENT) prefetchL1(&f14[(q1 & 0x7FFFF) * 8]);

    int swz = (lane & 7) * 4;

    #pragma unroll 1
    for (int k = 0; k < 27; k++) {
        bool take = ((q0 >> 19) == (unsigned)k);
        unsigned mask = __ballot_sync(FULLW, take);
        if (mask) {
            const float* wrow = &smw[(k * 32 + lane) * 32];
            float4 w0 = *(const float4*)&wrow[(0 * 4) ^ swz];
            float4 w1 = *(const float4*)&wrow[(1 * 4) ^ swz];
            float4 w2 = *(const float4*)&wrow[(2 * 4) ^ swz];
            float4 w3 = *(const float4*)&wrow[(3 * 4) ^ swz];
            float4 w4 = *(const float4*)&wrow[(4 * 4) ^ swz];
            float4 w5 = *(const float4*)&wrow[(5 * 4) ^ swz];
            float4 w6 = *(const float4*)&wrow[(6 * 4) ^ swz];
            float4 w7 = *(const float4*)&wrow[(7 * 4) ^ swz];
            unsigned mm = mask;
            #pragma unroll 1
            while (mm) {
                int j0 = __ffs(mm) - 1; mm &= mm - 1;
                int j1 = -1;
                if (mm) { j1 = __ffs(mm) - 1; mm &= mm - 1; }
                int i0 = __shfl_sync(FULLW, (int)q0, j0) & 0x7FFFF;
                int i1 = __shfl_sync(FULLW, (int)q0, (j1 >= 0) ? j1 : j0) & 0x7FFFF;
                const float4* fp0 = &f14[i0 * 8];
                const float4* fp1 = &f14[i1 * 8];
                // issue BOTH pairs' loads before either chain
                float4 a0 = __ldg(fp0 + 0), a1 = __ldg(fp0 + 1);
                float4 a2 = __ldg(fp0 + 2), a3 = __ldg(fp0 + 3);
                float4 a4 = __ldg(fp0 + 4), a5 = __ldg(fp0 + 5);
                float4 a6 = __ldg(fp0 + 6), a7 = __ldg(fp0 + 7);
                float4 b0, b1_, b2, b3, b4, b5, b6, b7;
                if (j1 >= 0) {
                    b0 = __ldg(fp1 + 0); b1_ = __ldg(fp1 + 1);
                    b2 = __ldg(fp1 + 2); b3 = __ldg(fp1 + 3);
                    b4 = __ldg(fp1 + 4); b5 = __ldg(fp1 + 5);
                    b6 = __ldg(fp1 + 6); b7 = __ldg(fp1 + 7);
                }
                float r0 = 0.f;
                r0 = fmaf(a0.x, w0.x, r0); r0 = fmaf(a0.y, w0.y, r0);
                r0 = fmaf(a0.z, w0.z, r0); r0 = fmaf(a0.w, w0.w, r0);
                r0 = fmaf(a1.x, w1.x, r0); r0 = fmaf(a1.y, w1.y, r0);
                r0 = fmaf(a1.z, w1.z, r0); r0 = fmaf(a1.w, w1.w, r0);
                r0 = fmaf(a2.x, w2.x, r0); r0 = fmaf(a2.y, w2.y, r0);
                r0 = fmaf(a2.z, w2.z, r0); r0 = fmaf(a2.w, w2.w, r0);
                r0 = fmaf(a3.x, w3.x, r0); r0 = fmaf(a3.y, w3.y, r0);
                r0 = fmaf(a3.z, w3.z, r0); r0 = fmaf(a3.w, w3.w, r0);
                r0 = fmaf(a4.x, w4.x, r0); r0 = fmaf(a4.y, w4.y, r0);
                r0 = fmaf(a4.z, w4.z, r0); r0 = fmaf(a4.w, w4.w, r0);
                r0 = fmaf(a5.x, w5.x, r0); r0 = fmaf(a5.y, w5.y, r0);
                r0 = fmaf(a5.z, w5.z, r0); r0 = fmaf(a5.w, w5.w, r0);
                r0 = fmaf(a6.x, w6.x, r0); r0 = fmaf(a6.y, w6.y, r0);
                r0 = fmaf(a6.z, w6.z, r0); r0 = fmaf(a6.w, w6.w, r0);
                r0 = fmaf(a7.x, w7.x, r0); r0 = fmaf(a7.y, w7.y, r0);
                r0 = fmaf(a7.z, w7.z, r0); r0 = fmaf(a7.w, w7.w, r0);
                sacc[j0 * 32 + lane] += r0;
                if (j1 >= 0) {
                    float r1 = 0.f;
                    r1 = fmaf(b0.x, w0.x, r1); r1 = fmaf(b0.y, w0.y, r1);
                    r1 = fmaf(b0.z, w0.z, r1); r1 = fmaf(b0.w, w0.w, r1);
                    r1 = fmaf(b1_.x, w1.x, r1); r1 = fmaf(b1_.y, w1.y, r1);
                    r1 = fmaf(b1_.z, w1.z, r1); r1 = fmaf(b1_.w, w1.w, r1);
                    r1 = fmaf(b2.x, w2.x, r1); r1 = fmaf(b2.y, w2.y, r1);
                    r1 = fmaf(b2.z, w2.z, r1); r1 = fmaf(b2.w, w2.w, r1);
                    r1 = fmaf(b3.x, w3.x, r1); r1 = fmaf(b3.y, w3.y, r1);
                    r1 = fmaf(b3.z, w3.z, r1); r1 = fmaf(b3.w, w3.w, r1);
                    r1 = fmaf(b4.x, w4.x, r1); r1 = fmaf(b4.y, w4.y, r1);
                    r1 = fmaf(b4.z, w4.z, r1); r1 = fmaf(b4.w, w4.w, r1);
                    r1 = fmaf(b5.x, w5.x, r1); r1 = fmaf(b5.y, w5.y, r1);
                    r1 = fmaf(b5.z, w5.z, r1); r1 = fmaf(b5.w, w5.w, r1);
                    r1 = fmaf(b6.x, w6.x, r1); r1 = fmaf(b6.y, w6.y, r1);
                    r1 = fmaf(b6.z, w6.z, r1); r1 = fmaf(b6.w, w6.w, r1);
                    r1 = fmaf(b7.x, w7.x, r1); r1 = fmaf(b7.y, w7.y, r1);
                    r1 = fmaf(b7.z, w7.z, r1); r1 = fmaf(b7.w, w7.w, r1);
                    sacc[j1 * 32 + lane] += r1;
                }
            }
        }
        if (take) {   // static shift-register consume; lazy tail refill
            q0 = q1; q1 = q2; q2 = q3; q3 = q4;
            q4 = q5; q5 = q6; q6 = q7;
            q7 = (e < cnt) ? __ldg(&g_rb[e * NMAX + row]) : SENT;
            e++;
            if (q1 != SENT) prefetchL1(&f14[(q1 & 0x7FFFF) * 8]);
        }
    }

    int co = half * 32 + lane;
    float s  = g2[co] * rsqrtf(v2[co] + BN_EPS);
    float sh = b2[co] - m2[co] * s;
    #pragma unroll
    for (int r = 0; r < 32; r++) {
        int rr = row0 + r;
        if (rr < m) {
            float o = fmaf(sacc[r * 32 + lane], s, sh);
            out[rr * C2 + co] = o > 0.f ? o : 0.f;
        }
    }
}

// ---------------------------------------------------------------------------
// Tail: fill everything past f2 (out_coors as float, batch_size) if the
// harness flattened the full reference tuple into d_out.
// ---------------------------------------------------------------------------
__global__ void tail_kernel(const int* __restrict__ ocoors,
                            const int* __restrict__ bsz,
                            float* __restrict__ out, int m, int total)
{
    int i = blockIdx.x * blockDim.x + threadIdx.x + m * 64;
    if (i >= total) return;
    int j = i - m * 64;
    float v;
    if (j < m * 4)       v = (float)ocoors[j];
    else if (j == m * 4) v = (float)bsz[0];
    else                 v = 0.f;
    out[i] = v;
}

// ---------------------------------------------------------------------------
extern "C" void kernel_launch(void* const* d_in, const int* in_sizes, int n_in,
                              void* d_out, int out_size)
{
    const float* feat   = (const float*)d_in[0];
    const int*   coors  = (const int*)d_in[1];
    const int*   ocoors = (const int*)d_in[2];
    const float* W1     = (const float*)d_in[3];
    const float* g1     = (const float*)d_in[4];
    const float* b1     = (const float*)d_in[5];
    const float* m1     = (const float*)d_in[6];
    const float* v1     = (const float*)d_in[7];
    const float* W2     = (const float*)d_in[8];
    const float* g2     = (const float*)d_in[9];
    const float* b2     = (const float*)d_in[10];
    const float* m2     = (const float*)d_in[11];
    const float* v2     = (const float*)d_in[12];
    const int*   bsz    = (const int*)d_in[13];

    int n = in_sizes[0] / CIN;
    int m = in_sizes[2] / 4;

    fill_grid_kernel<<<(GRID_SZ / 4 + 255) / 256, 256>>>();
    scatter_kernel<<<(n + 255) / 256, 256>>>(coors, n);

    // layer 1 (inline probes, no rulebook)
    int smem1 = 27 * C1 * 32 * (int)sizeof(float);   // 110,592 B
    cudaFuncSetAttribute(conv1_kernel, cudaFuncAttributeMaxDynamicSharedMemorySize, smem1);
    conv1_kernel<<<(n + 255) / 256, 512, smem1>>>(feat, coors, W1, g1, b1, m1, v1, n);

    // layer 2: rulebook, then conv with smem accumulators + pipelined pair loop
    rb2_build_kernel<<<(m + 255) / 256, 256>>>(ocoors, m);
    int smem2 = (CONV2_W_ELEMS + 16 * 32 * 32) * (int)sizeof(float);   // 176,128 B
    cudaFuncSetAttribute(conv2_kernel, cudaFuncAttributeMaxDynamicSharedMemorySize, smem2);
    int rowblocks = (m + 511) / 512;
    conv2_kernel<<<rowblocks * 2, 512, smem2>>>(W2, g2, b2, m2, v2, (float*)d_out, m);

    int tail = out_size - m * 64;
    if (tail > 0) {
        tail_kernel<<<(tail + 255) / 256, 256>>>(ocoors, bsz, (float*)d_out, m, out_size);
    }
}